// round 2
// baseline (speedup 1.0000x reference)
#include <cuda_runtime.h>
#include <math.h>

#define T_TOK    4096
#define DM       1024      // d_model
#define DH       4096      // d_hidden
#define NE       8
#define NASSIGN  (T_TOK * 2)

// ---------------- static device scratch (no allocations allowed) ----------------
__device__ float g_H[(size_t)NASSIGN * DH];   // gathered hidden activations [8192, 4096]
__device__ int   g_tok[NASSIGN];              // token id per assignment slot (compact per expert)
__device__ float g_wgt[NASSIGN];              // combine weight per assignment slot
__device__ int   g_eid[NASSIGN];              // per-token chosen experts (2 per token)
__device__ float g_ew [NASSIGN];              // per-token weights (2 per token)
__device__ int   g_cnt[NE];
__device__ int   g_off[NE];
__device__ int   g_cur[NE];

// ---------------- init / zero ----------------
__global__ void k_init() {
    if (threadIdx.x < NE) g_cnt[threadIdx.x] = 0;
}

__global__ void k_zero_out(float* __restrict__ out) {
    size_t i = (size_t)blockIdx.x * blockDim.x + threadIdx.x;
    if (i < (size_t)T_TOK * DM / 4) {
        float4 z = make_float4(0.f, 0.f, 0.f, 0.f);
        reinterpret_cast<float4*>(out)[i] = z;
    }
}

// ---------------- gating: logits, top-2, softmax ----------------
// one warp per token; 8 warps per block
__global__ void k_gate(const float* __restrict__ x, const float* __restrict__ Wg,
                       const float* __restrict__ bg, float* __restrict__ out_logits) {
    int warp = threadIdx.x >> 5, lane = threadIdx.x & 31;
    int t = blockIdx.x * 8 + warp;
    if (t >= T_TOK) return;

    const float* xr = x + (size_t)t * DM;
    float acc[NE];
#pragma unroll
    for (int e = 0; e < NE; e++) acc[e] = 0.f;

    for (int k = lane; k < DM; k += 32) {
        float xv = xr[k];
        const float* w = Wg + (size_t)k * NE;
#pragma unroll
        for (int e = 0; e < NE; e++) acc[e] += xv * w[e];
    }
#pragma unroll
    for (int e = 0; e < NE; e++)
#pragma unroll
        for (int o = 16; o; o >>= 1) acc[e] += __shfl_xor_sync(0xffffffffu, acc[e], o);

    if (lane == 0) {
#pragma unroll
        for (int e = 0; e < NE; e++) {
            acc[e] += bg[e];
            out_logits[(size_t)t * NE + e] = acc[e];
        }
        // top-2 (lowest index wins ties, matching jax.lax.top_k)
        int b0 = 0;
#pragma unroll
        for (int e = 1; e < NE; e++) if (acc[e] > acc[b0]) b0 = e;
        int b1 = (b0 == 0) ? 1 : 0;
#pragma unroll
        for (int e = 0; e < NE; e++) if (e != b0 && acc[e] > acc[b1]) b1 = e;

        float ex = expf(acc[b1] - acc[b0]);   // <= 1
        float w0 = 1.f / (1.f + ex);
        float w1 = ex * w0;

        g_eid[2 * t]     = b0;  g_ew[2 * t]     = w0;
        g_eid[2 * t + 1] = b1;  g_ew[2 * t + 1] = w1;
        atomicAdd(&g_cnt[b0], 1);
        atomicAdd(&g_cnt[b1], 1);
    }
}

__global__ void k_offsets() {
    if (threadIdx.x == 0) {
        int s = 0;
#pragma unroll
        for (int e = 0; e < NE; e++) { g_off[e] = s; g_cur[e] = s; s += g_cnt[e]; }
    }
}

__global__ void k_scatter() {
    int a = blockIdx.x * blockDim.x + threadIdx.x;
    if (a < NASSIGN) {
        int e = g_eid[a];
        int pos = atomicAdd(&g_cur[e], 1);
        g_tok[pos] = a >> 1;
        g_wgt[pos] = g_ew[a];
    }
}

// ---------------- GEMM1: H[slot, :] = relu(x[tok] @ W1[e] + b1[e]) ----------------
// 128x128 tile, BK=8, 256 threads, 8x8 per thread
__global__ void __launch_bounds__(256, 2)
k_gemm1(const float* __restrict__ x, const float* __restrict__ W1,
        const float* __restrict__ b1) {
    const int e   = blockIdx.z;
    const int cnt = g_cnt[e];
    const int m0  = blockIdx.y * 128;
    if (m0 >= cnt) return;
    const int off = g_off[e];
    const int n0  = blockIdx.x * 128;
    const float* W = W1 + (size_t)e * DM * DH;

    __shared__ float As[8][128];
    __shared__ float Bs[8][128];

    const int tid  = threadIdx.x;
    const int aRow = tid >> 1;          // 0..127
    const int aK   = (tid & 1) * 4;     // 0 or 4
    const int bRow = tid >> 5;          // 0..7
    const int bCol = (tid & 31) * 4;    // 0..124
    const int rc   = (tid >> 4) * 8;    // acc row base
    const int cc   = (tid & 15) * 8;    // acc col base

    const int gRow = m0 + aRow;
    const float* arow = nullptr;
    if (gRow < cnt) arow = x + (size_t)g_tok[off + gRow] * DM;

    float acc[8][8];
#pragma unroll
    for (int i = 0; i < 8; i++)
#pragma unroll
        for (int j = 0; j < 8; j++) acc[i][j] = 0.f;

    for (int k0 = 0; k0 < DM; k0 += 8) {
        float4 av = make_float4(0.f, 0.f, 0.f, 0.f);
        if (arow) av = *reinterpret_cast<const float4*>(arow + k0 + aK);
        float4 bv = *reinterpret_cast<const float4*>(W + (size_t)(k0 + bRow) * DH + n0 + bCol);

        __syncthreads();
        As[aK + 0][aRow] = av.x;
        As[aK + 1][aRow] = av.y;
        As[aK + 2][aRow] = av.z;
        As[aK + 3][aRow] = av.w;
        *reinterpret_cast<float4*>(&Bs[bRow][bCol]) = bv;
        __syncthreads();

#pragma unroll
        for (int kk = 0; kk < 8; kk++) {
            float a[8], b[8];
            *reinterpret_cast<float4*>(a)     = *reinterpret_cast<const float4*>(&As[kk][rc]);
            *reinterpret_cast<float4*>(a + 4) = *reinterpret_cast<const float4*>(&As[kk][rc + 4]);
            *reinterpret_cast<float4*>(b)     = *reinterpret_cast<const float4*>(&Bs[kk][cc]);
            *reinterpret_cast<float4*>(b + 4) = *reinterpret_cast<const float4*>(&Bs[kk][cc + 4]);
#pragma unroll
            for (int i = 0; i < 8; i++)
#pragma unroll
                for (int j = 0; j < 8; j++) acc[i][j] += a[i] * b[j];
        }
    }

    float bias[8];
#pragma unroll
    for (int j = 0; j < 8; j++) bias[j] = b1[(size_t)e * DH + n0 + cc + j];

#pragma unroll
    for (int i = 0; i < 8; i++) {
        int gi = m0 + rc + i;
        if (gi < cnt) {
            float* hrow = g_H + (size_t)(off + gi) * DH + n0 + cc;
#pragma unroll
            for (int j = 0; j < 8; j++) {
                float v = acc[i][j] + bias[j];
                hrow[j] = v > 0.f ? v : 0.f;
            }
        }
    }
}

// ---------------- GEMM2: out[tok] += w * (H[slot] @ W2[e] + b2[e]) ----------------
__global__ void __launch_bounds__(256, 2)
k_gemm2(const float* __restrict__ W2, const float* __restrict__ b2,
        float* __restrict__ out) {
    const int e   = blockIdx.z;
    const int cnt = g_cnt[e];
    const int m0  = blockIdx.y * 128;
    if (m0 >= cnt) return;
    const int off = g_off[e];
    const int n0  = blockIdx.x * 128;
    const float* W = W2 + (size_t)e * DH * DM;

    __shared__ float As[8][128];
    __shared__ float Bs[8][128];

    const int tid  = threadIdx.x;
    const int aRow = tid >> 1;
    const int aK   = (tid & 1) * 4;
    const int bRow = tid >> 5;
    const int bCol = (tid & 31) * 4;
    const int rc   = (tid >> 4) * 8;
    const int cc   = (tid & 15) * 8;

    const int gRow = m0 + aRow;
    const float* arow = nullptr;
    if (gRow < cnt) arow = g_H + (size_t)(off + gRow) * DH;

    float acc[8][8];
#pragma unroll
    for (int i = 0; i < 8; i++)
#pragma unroll
        for (int j = 0; j < 8; j++) acc[i][j] = 0.f;

    for (int k0 = 0; k0 < DH; k0 += 8) {
        float4 av = make_float4(0.f, 0.f, 0.f, 0.f);
        if (arow) av = *reinterpret_cast<const float4*>(arow + k0 + aK);
        float4 bv = *reinterpret_cast<const float4*>(W + (size_t)(k0 + bRow) * DM + n0 + bCol);

        __syncthreads();
        As[aK + 0][aRow] = av.x;
        As[aK + 1][aRow] = av.y;
        As[aK + 2][aRow] = av.z;
        As[aK + 3][aRow] = av.w;
        *reinterpret_cast<float4*>(&Bs[bRow][bCol]) = bv;
        __syncthreads();

#pragma unroll
        for (int kk = 0; kk < 8; kk++) {
            float a[8], b[8];
            *reinterpret_cast<float4*>(a)     = *reinterpret_cast<const float4*>(&As[kk][rc]);
            *reinterpret_cast<float4*>(a + 4) = *reinterpret_cast<const float4*>(&As[kk][rc + 4]);
            *reinterpret_cast<float4*>(b)     = *reinterpret_cast<const float4*>(&Bs[kk][cc]);
            *reinterpret_cast<float4*>(b + 4) = *reinterpret_cast<const float4*>(&Bs[kk][cc + 4]);
#pragma unroll
            for (int i = 0; i < 8; i++)
#pragma unroll
                for (int j = 0; j < 8; j++) acc[i][j] += a[i] * b[j];
        }
    }

    float bias[8];
#pragma unroll
    for (int j = 0; j < 8; j++) bias[j] = b2[(size_t)e * DM + n0 + cc + j];

#pragma unroll
    for (int i = 0; i < 8; i++) {
        int gi = m0 + rc + i;
        if (gi < cnt) {
            int   tok = g_tok[off + gi];
            float w   = g_wgt[off + gi];
            float* orow = out + (size_t)tok * DM + n0 + cc;
#pragma unroll
            for (int j = 0; j < 8; j++) {
                atomicAdd(&orow[j], w * (acc[i][j] + bias[j]));
            }
        }
    }
}

// ---------------- launch ----------------
extern "C" void kernel_launch(void* const* d_in, const int* in_sizes, int n_in,
                              void* d_out, int out_size) {
    const float* x  = (const float*)d_in[0];
    const float* Wg = (const float*)d_in[1];
    const float* bg = (const float*)d_in[2];
    const float* W1 = (const float*)d_in[3];
    const float* b1 = (const float*)d_in[4];
    const float* W2 = (const float*)d_in[5];
    const float* b2 = (const float*)d_in[6];
    float* out = (float*)d_out;

    k_init<<<1, 32>>>();
    k_zero_out<<<(T_TOK * DM / 4 + 255) / 256, 256>>>(out);
    k_gate<<<T_TOK / 8, 256>>>(x, Wg, bg, out + (size_t)T_TOK * DM);
    k_offsets<<<1, 32>>>();
    k_scatter<<<(NASSIGN + 255) / 256, 256>>>();
    k_gemm1<<<dim3(DH / 128, T_TOK / 128, NE), 256>>>(x, W1, b1);
    k_gemm2<<<dim3(DM / 128, T_TOK / 128, NE), 256>>>(W2, b2, out);
}

// round 4
// speedup vs baseline: 1.4918x; 1.4918x over previous
#include <cuda_runtime.h>
#include <cuda_bf16.h>
#include <cstdint>
#include <math.h>

#define T_TOK    4096
#define DM       1024
#define DH       4096
#define NE       8
#define NASSIGN  (T_TOK * 2)

#define KC   16            // k per chunk
#define PA   24            // A smem pitch (bf16 elems), 16 + 8 pad
#define PB   136           // B smem pitch (bf16 elems), 128 + 8 pad

// ---------------- static device scratch ----------------
__device__ float g_H[(size_t)NASSIGN * DH];
__device__ int   g_tok[NASSIGN];
__device__ float g_wgt[NASSIGN];
__device__ int   g_eid[NASSIGN];
__device__ float g_ew [NASSIGN];
__device__ int   g_cnt[NE];
__device__ int   g_off[NE];
__device__ int   g_cur[NE];

// ---------------- helpers ----------------
__device__ __forceinline__ uint32_t smem_u32(const void* p) {
    uint32_t a;
    asm("{ .reg .u64 t; cvta.to.shared.u64 t, %1; cvt.u32.u64 %0, t; }" : "=r"(a) : "l"(p));
    return a;
}

__device__ __forceinline__ void split_pack(float4 v, uint2& hi, uint2& lo) {
    __nv_bfloat16 hx = __float2bfloat16(v.x), hy = __float2bfloat16(v.y);
    __nv_bfloat16 hz = __float2bfloat16(v.z), hw = __float2bfloat16(v.w);
    __nv_bfloat16 lx = __float2bfloat16(v.x - __bfloat162float(hx));
    __nv_bfloat16 ly = __float2bfloat16(v.y - __bfloat162float(hy));
    __nv_bfloat16 lz = __float2bfloat16(v.z - __bfloat162float(hz));
    __nv_bfloat16 lw = __float2bfloat16(v.w - __bfloat162float(hw));
    __nv_bfloat162 h01 = __halves2bfloat162(hx, hy), h23 = __halves2bfloat162(hz, hw);
    __nv_bfloat162 l01 = __halves2bfloat162(lx, ly), l23 = __halves2bfloat162(lz, lw);
    hi.x = *(uint32_t*)&h01; hi.y = *(uint32_t*)&h23;
    lo.x = *(uint32_t*)&l01; lo.y = *(uint32_t*)&l23;
}

__device__ __forceinline__ void ldsm_x4(uint32_t (&d)[4], uint32_t addr) {
    asm volatile("ldmatrix.sync.aligned.m8n8.x4.shared.b16 {%0,%1,%2,%3}, [%4];"
        : "=r"(d[0]), "=r"(d[1]), "=r"(d[2]), "=r"(d[3]) : "r"(addr));
}
__device__ __forceinline__ void ldsm_x4t(uint32_t (&d)[4], uint32_t addr) {
    asm volatile("ldmatrix.sync.aligned.m8n8.x4.trans.shared.b16 {%0,%1,%2,%3}, [%4];"
        : "=r"(d[0]), "=r"(d[1]), "=r"(d[2]), "=r"(d[3]) : "r"(addr));
}
__device__ __forceinline__ void mma_bf16(float (&d)[4], const uint32_t (&a)[4],
                                          uint32_t b0, uint32_t b1) {
    asm volatile("mma.sync.aligned.m16n8k16.row.col.f32.bf16.bf16.f32 "
        "{%0,%1,%2,%3},{%4,%5,%6,%7},{%8,%9},{%0,%1,%2,%3};"
        : "+f"(d[0]), "+f"(d[1]), "+f"(d[2]), "+f"(d[3])
        : "r"(a[0]), "r"(a[1]), "r"(a[2]), "r"(a[3]), "r"(b0), "r"(b1));
}

// ---------------- shared memory (static, 44 KB < 48 KB) ----------------
struct SmemT {
    const float* rowp[128];
    int          toks[128];
    float        wgts[128];
    __nv_bfloat16 A[2][2][128 * PA];   // [buf][hi/lo]
    __nv_bfloat16 B[2][2][KC * PB];
};

// ---------------- shared pipelined mainloop ----------------
// acc[mi][ni][4]: D[128,128] for this CTA; A rows via sm.rowp (nullptr -> 0)
__device__ __forceinline__ void mainloop(SmemT& sm, const float* __restrict__ Bmat,
                                          int ldb, int n0, int nch,
                                          float (&acc)[4][4][4]) {
    const int tid  = threadIdx.x;
    const int lane = tid & 31, w = tid >> 5;
    const int m_warp = (w >> 2) * 64, n_warp = (w & 3) * 32;
    const int g = lane >> 3, r = lane & 7;

    const int a_row = tid >> 2, a_k4 = tid & 3;
    const int b_k   = tid >> 5, b_n4 = tid & 31;

    // lane-invariant ldmatrix offsets (bytes)
    const uint32_t a_lane = (uint32_t)(((m_warp + (g & 1) * 8 + r) * PA + (g >> 1) * 8) * 2);
    const uint32_t b_lane = (uint32_t)((((g & 1) * 8 + r) * PB + n_warp + (g >> 1) * 8) * 2);

    uint32_t Ab[2][2], Bb[2][2];
#pragma unroll
    for (int b = 0; b < 2; b++)
#pragma unroll
        for (int t = 0; t < 2; t++) {
            Ab[b][t] = smem_u32(sm.A[b][t]) + a_lane;
            Bb[b][t] = smem_u32(sm.B[b][t]) + b_lane;
        }

    float4 rA[2], rB[2];

#define LDG_CHUNK(c) do { \
        int k0 = (c) * KC; \
        _Pragma("unroll") \
        for (int i = 0; i < 2; i++) { \
            const float* rp = sm.rowp[a_row + 64 * i]; \
            rA[i] = rp ? *(const float4*)(rp + k0 + a_k4 * 4) \
                       : make_float4(0.f, 0.f, 0.f, 0.f); \
            rB[i] = *(const float4*)(Bmat + (size_t)(k0 + b_k + 8 * i) * ldb + n0 + b_n4 * 4); \
        } \
    } while (0)

#define STS_CHUNK(bf) do { \
        _Pragma("unroll") \
        for (int i = 0; i < 2; i++) { \
            uint2 hi, lo; \
            split_pack(rA[i], hi, lo); \
            int offA = (a_row + 64 * i) * PA + a_k4 * 4; \
            *(uint2*)&sm.A[bf][0][offA] = hi; \
            *(uint2*)&sm.A[bf][1][offA] = lo; \
            split_pack(rB[i], hi, lo); \
            int offB = (b_k + 8 * i) * PB + b_n4 * 4; \
            *(uint2*)&sm.B[bf][0][offB] = hi; \
            *(uint2*)&sm.B[bf][1][offB] = lo; \
        } \
    } while (0)

    LDG_CHUNK(0);
    STS_CHUNK(0);
    __syncthreads();

    for (int c = 0; c < nch; c++) {
        const int bf = c & 1;
        if (c + 1 < nch) LDG_CHUNK(c + 1);

        uint32_t ah[4][4], al[4][4], bh[2][4], bl[2][4];
#pragma unroll
        for (int mi = 0; mi < 4; mi++) {
            ldsm_x4(ah[mi], Ab[bf][0] + mi * (16 * PA * 2));
            ldsm_x4(al[mi], Ab[bf][1] + mi * (16 * PA * 2));
        }
#pragma unroll
        for (int nj = 0; nj < 2; nj++) {
            ldsm_x4t(bh[nj], Bb[bf][0] + nj * 32);
            ldsm_x4t(bl[nj], Bb[bf][1] + nj * 32);
        }
#pragma unroll
        for (int mi = 0; mi < 4; mi++)
#pragma unroll
            for (int nj = 0; nj < 2; nj++)
#pragma unroll
                for (int h = 0; h < 2; h++) {
                    int ni = nj * 2 + h;
                    mma_bf16(acc[mi][ni], ah[mi], bh[nj][h * 2], bh[nj][h * 2 + 1]);
                    mma_bf16(acc[mi][ni], ah[mi], bl[nj][h * 2], bl[nj][h * 2 + 1]);
                    mma_bf16(acc[mi][ni], al[mi], bh[nj][h * 2], bh[nj][h * 2 + 1]);
                }

        if (c + 1 < nch) STS_CHUNK((c + 1) & 1);
        __syncthreads();
    }
#undef LDG_CHUNK
#undef STS_CHUNK
}

// ---------------- init / zero / gating / routing ----------------
__global__ void k_init() { if (threadIdx.x < NE) g_cnt[threadIdx.x] = 0; }

__global__ void k_zero_out(float* __restrict__ out) {
    size_t i = (size_t)blockIdx.x * blockDim.x + threadIdx.x;
    if (i < (size_t)T_TOK * DM / 4)
        reinterpret_cast<float4*>(out)[i] = make_float4(0.f, 0.f, 0.f, 0.f);
}

__global__ void k_gate(const float* __restrict__ x, const float* __restrict__ Wg,
                       const float* __restrict__ bg, float* __restrict__ out_logits) {
    int warp = threadIdx.x >> 5, lane = threadIdx.x & 31;
    int t = blockIdx.x * 8 + warp;
    if (t >= T_TOK) return;
    const float* xr = x + (size_t)t * DM;
    float acc[NE];
#pragma unroll
    for (int e = 0; e < NE; e++) acc[e] = 0.f;
    for (int k = lane; k < DM; k += 32) {
        float xv = xr[k];
        const float* w = Wg + (size_t)k * NE;
#pragma unroll
        for (int e = 0; e < NE; e++) acc[e] += xv * w[e];
    }
#pragma unroll
    for (int e = 0; e < NE; e++)
#pragma unroll
        for (int o = 16; o; o >>= 1) acc[e] += __shfl_xor_sync(0xffffffffu, acc[e], o);
    if (lane == 0) {
#pragma unroll
        for (int e = 0; e < NE; e++) {
            acc[e] += bg[e];
            out_logits[(size_t)t * NE + e] = acc[e];
        }
        int b0 = 0;
#pragma unroll
        for (int e = 1; e < NE; e++) if (acc[e] > acc[b0]) b0 = e;
        int b1 = (b0 == 0) ? 1 : 0;
#pragma unroll
        for (int e = 0; e < NE; e++) if (e != b0 && acc[e] > acc[b1]) b1 = e;
        float ex = expf(acc[b1] - acc[b0]);
        float w0 = 1.f / (1.f + ex);
        float w1 = ex * w0;
        g_eid[2 * t] = b0;     g_ew[2 * t] = w0;
        g_eid[2 * t + 1] = b1; g_ew[2 * t + 1] = w1;
        atomicAdd(&g_cnt[b0], 1);
        atomicAdd(&g_cnt[b1], 1);
    }
}

__global__ void k_offsets() {
    if (threadIdx.x == 0) {
        int s = 0;
#pragma unroll
        for (int e = 0; e < NE; e++) { g_off[e] = s; g_cur[e] = s; s += g_cnt[e]; }
    }
}

__global__ void k_scatter() {
    int a = blockIdx.x * blockDim.x + threadIdx.x;
    if (a < NASSIGN) {
        int e = g_eid[a];
        int pos = atomicAdd(&g_cur[e], 1);
        g_tok[pos] = a >> 1;
        g_wgt[pos] = g_ew[a];
    }
}

// ---------------- GEMM1 (mma.sync): H = relu(x_gathered @ W1[e] + b1[e]) ----------------
__global__ void __launch_bounds__(256, 1)
k_gemm1_mma(const float* __restrict__ x, const float* __restrict__ W1,
            const float* __restrict__ b1) {
    __shared__ SmemT sm;
    const int e = blockIdx.z;
    const int cnt = g_cnt[e];
    const int m0 = blockIdx.y * 128;
    if (m0 >= cnt) return;
    const int off = g_off[e];
    const int n0 = blockIdx.x * 128;
    const int tid = threadIdx.x;

    if (tid < 128) {
        int gi = m0 + tid;
        sm.rowp[tid] = (gi < cnt) ? x + (size_t)g_tok[off + gi] * DM : (const float*)0;
    }
    __syncthreads();

    float acc[4][4][4];
#pragma unroll
    for (int a = 0; a < 4; a++)
#pragma unroll
        for (int b = 0; b < 4; b++)
#pragma unroll
            for (int c = 0; c < 4; c++) acc[a][b][c] = 0.f;

    mainloop(sm, W1 + (size_t)e * DM * DH, DH, n0, DM / KC, acc);

    const int lane = tid & 31, w = tid >> 5;
    const int m_warp = (w >> 2) * 64, n_warp = (w & 3) * 32;
    const float* bb = b1 + (size_t)e * DH;
#pragma unroll
    for (int mi = 0; mi < 4; mi++) {
#pragma unroll
        for (int ni = 0; ni < 4; ni++) {
            int col = n0 + n_warp + ni * 8 + (lane & 3) * 2;
            float bc0 = bb[col], bc1 = bb[col + 1];
#pragma unroll
            for (int hr = 0; hr < 2; hr++) {
                int lr = m_warp + mi * 16 + (lane >> 2) + hr * 8;
                int gi = m0 + lr;
                if (gi < cnt) {
                    float2 o;
                    o.x = fmaxf(acc[mi][ni][hr * 2 + 0] + bc0, 0.f);
                    o.y = fmaxf(acc[mi][ni][hr * 2 + 1] + bc1, 0.f);
                    *(float2*)(g_H + (size_t)(off + gi) * DH + col) = o;
                }
            }
        }
    }
}

// ---------------- GEMM2 (mma.sync): out[tok] += w * (H @ W2[e] + b2[e]) ----------------
__global__ void __launch_bounds__(256, 1)
k_gemm2_mma(const float* __restrict__ W2, const float* __restrict__ b2,
            float* __restrict__ out) {
    __shared__ SmemT sm;
    const int e = blockIdx.z;
    const int cnt = g_cnt[e];
    const int m0 = blockIdx.y * 128;
    if (m0 >= cnt) return;
    const int off = g_off[e];
    const int n0 = blockIdx.x * 128;
    const int tid = threadIdx.x;

    if (tid < 128) {
        int gi = m0 + tid;
        bool v = gi < cnt;
        sm.rowp[tid] = v ? g_H + (size_t)(off + gi) * DH : (const float*)0;
        sm.toks[tid] = v ? g_tok[off + gi] : 0;
        sm.wgts[tid] = v ? g_wgt[off + gi] : 0.f;
    }
    __syncthreads();

    float acc[4][4][4];
#pragma unroll
    for (int a = 0; a < 4; a++)
#pragma unroll
        for (int b = 0; b < 4; b++)
#pragma unroll
            for (int c = 0; c < 4; c++) acc[a][b][c] = 0.f;

    mainloop(sm, W2 + (size_t)e * DH * DM, DM, n0, DH / KC, acc);

    const int lane = tid & 31, w = tid >> 5;
    const int m_warp = (w >> 2) * 64, n_warp = (w & 3) * 32;
    const float* bb = b2 + (size_t)e * DM;
#pragma unroll
    for (int mi = 0; mi < 4; mi++) {
#pragma unroll
        for (int ni = 0; ni < 4; ni++) {
            int col = n0 + n_warp + ni * 8 + (lane & 3) * 2;
            float bc0 = bb[col], bc1 = bb[col + 1];
#pragma unroll
            for (int hr = 0; hr < 2; hr++) {
                int lr = m_warp + mi * 16 + (lane >> 2) + hr * 8;
                int gi = m0 + lr;
                if (gi < cnt) {
                    int tok  = sm.toks[lr];
                    float wv = sm.wgts[lr];
                    float* orow = out + (size_t)tok * DM + col;
                    atomicAdd(orow,     wv * (acc[mi][ni][hr * 2 + 0] + bc0));
                    atomicAdd(orow + 1, wv * (acc[mi][ni][hr * 2 + 1] + bc1));
                }
            }
        }
    }
}

// ---------------- launch ----------------
extern "C" void kernel_launch(void* const* d_in, const int* in_sizes, int n_in,
                              void* d_out, int out_size) {
    const float* x  = (const float*)d_in[0];
    const float* Wg = (const float*)d_in[1];
    const float* bg = (const float*)d_in[2];
    const float* W1 = (const float*)d_in[3];
    const float* b1 = (const float*)d_in[4];
    const float* W2 = (const float*)d_in[5];
    const float* b2 = (const float*)d_in[6];
    float* out = (float*)d_out;

    k_init<<<1, 32>>>();
    k_zero_out<<<(T_TOK * DM / 4 + 255) / 256, 256>>>(out);
    k_gate<<<T_TOK / 8, 256>>>(x, Wg, bg, out + (size_t)T_TOK * DM);
    k_offsets<<<1, 32>>>();
    k_scatter<<<(NASSIGN + 255) / 256, 256>>>();
    k_gemm1_mma<<<dim3(DH / 128, T_TOK / 128, NE), 256>>>(x, W1, b1);
    k_gemm2_mma<<<dim3(DM / 128, T_TOK / 128, NE), 256>>>(W2, b2, out);
}

// round 6
// speedup vs baseline: 2.0993x; 1.4072x over previous
#include <cuda_runtime.h>
#include <cuda_bf16.h>
#include <cstdint>
#include <math.h>

#define T_TOK    4096
#define DM       1024
#define DH       4096
#define NE       8
#define NASSIGN  (T_TOK * 2)

#define KC    32           // k per pipeline chunk
#define PA    40           // A smem pitch (bf16 elems): 32 + 8 pad
#define PB    136          // B smem pitch (bf16 elems): 128 + 8 pad
#define NSTG  3

// stage layout (bytes)
#define ST_AHI   0
#define ST_ALO   10240     // 128*PA*2
#define ST_BHI   20480
#define ST_BLO   29184     // +32*PB*2
#define ST_BYTES 37888
#define SM_HDR   2048
#define SMEM_TOTAL (SM_HDR + NSTG * ST_BYTES)   // 115712

#define INVALID_ROW 0xFFFFFFFFu

// ---------------- static device scratch ----------------
__device__ __nv_bfloat16 g_xhi[(size_t)T_TOK * DM];
__device__ __nv_bfloat16 g_xlo[(size_t)T_TOK * DM];
__device__ __nv_bfloat16 g_W1hi[(size_t)NE * DM * DH];
__device__ __nv_bfloat16 g_W1lo[(size_t)NE * DM * DH];
__device__ __nv_bfloat16 g_W2hi[(size_t)NE * DH * DM];
__device__ __nv_bfloat16 g_W2lo[(size_t)NE * DH * DM];
__device__ __nv_bfloat16 g_Hhi[(size_t)NASSIGN * DH];
__device__ __nv_bfloat16 g_Hlo[(size_t)NASSIGN * DH];
__device__ int   g_tok[NASSIGN];
__device__ float g_wgt[NASSIGN];
__device__ int   g_eid[NASSIGN];
__device__ float g_ew [NASSIGN];
__device__ int   g_cnt[NE];
__device__ int   g_off[NE];
__device__ int   g_cur[NE];

// ---------------- helpers ----------------
__device__ __forceinline__ uint32_t smem_u32(const void* p) {
    uint32_t a;
    asm("{ .reg .u64 t; cvta.to.shared.u64 t, %1; cvt.u32.u64 %0, t; }" : "=r"(a) : "l"(p));
    return a;
}
__device__ __forceinline__ void split_pack(float4 v, uint2& hi, uint2& lo) {
    __nv_bfloat16 hx = __float2bfloat16(v.x), hy = __float2bfloat16(v.y);
    __nv_bfloat16 hz = __float2bfloat16(v.z), hw = __float2bfloat16(v.w);
    __nv_bfloat16 lx = __float2bfloat16(v.x - __bfloat162float(hx));
    __nv_bfloat16 ly = __float2bfloat16(v.y - __bfloat162float(hy));
    __nv_bfloat16 lz = __float2bfloat16(v.z - __bfloat162float(hz));
    __nv_bfloat16 lw = __float2bfloat16(v.w - __bfloat162float(hw));
    __nv_bfloat162 h01 = __halves2bfloat162(hx, hy), h23 = __halves2bfloat162(hz, hw);
    __nv_bfloat162 l01 = __halves2bfloat162(lx, ly), l23 = __halves2bfloat162(lz, lw);
    hi.x = *(uint32_t*)&h01; hi.y = *(uint32_t*)&h23;
    lo.x = *(uint32_t*)&l01; lo.y = *(uint32_t*)&l23;
}
__device__ __forceinline__ void ldsm_x4(uint32_t (&d)[4], uint32_t addr) {
    asm volatile("ldmatrix.sync.aligned.m8n8.x4.shared.b16 {%0,%1,%2,%3}, [%4];"
        : "=r"(d[0]), "=r"(d[1]), "=r"(d[2]), "=r"(d[3]) : "r"(addr));
}
__device__ __forceinline__ void ldsm_x4t(uint32_t (&d)[4], uint32_t addr) {
    asm volatile("ldmatrix.sync.aligned.m8n8.x4.trans.shared.b16 {%0,%1,%2,%3}, [%4];"
        : "=r"(d[0]), "=r"(d[1]), "=r"(d[2]), "=r"(d[3]) : "r"(addr));
}
__device__ __forceinline__ void mma_bf16(float (&d)[4], const uint32_t (&a)[4],
                                          uint32_t b0, uint32_t b1) {
    asm volatile("mma.sync.aligned.m16n8k16.row.col.f32.bf16.bf16.f32 "
        "{%0,%1,%2,%3},{%4,%5,%6,%7},{%8,%9},{%0,%1,%2,%3};"
        : "+f"(d[0]), "+f"(d[1]), "+f"(d[2]), "+f"(d[3])
        : "r"(a[0]), "r"(a[1]), "r"(a[2]), "r"(a[3]), "r"(b0), "r"(b1));
}
__device__ __forceinline__ void cp16(uint32_t dst, const void* src, uint32_t sz) {
    asm volatile("cp.async.cg.shared.global [%0], [%1], 16, %2;"
                 :: "r"(dst), "l"(src), "r"(sz));
}
#define CP_COMMIT() asm volatile("cp.async.commit_group;" ::: "memory")
#define CP_WAIT2()  asm volatile("cp.async.wait_group 2;" ::: "memory")

// ---------------- issue one KC=32 chunk via cp.async ----------------
__device__ __forceinline__ void issue_chunk(
    uint32_t st, const __nv_bfloat16* __restrict__ Ahi, const __nv_bfloat16* __restrict__ Alo,
    const uint32_t* __restrict__ rowoff,
    const __nv_bfloat16* __restrict__ Bhi, const __nv_bfloat16* __restrict__ Blo,
    int ldb, int n0, int k0, int tid)
{
    // A: 128 rows x 32 k; thread -> (row = tid>>1, 32B-half = tid&1)
    const int ar = tid >> 1, ahalf = tid & 1;
    uint32_t ro = rowoff[ar];
    uint32_t sz = (ro != INVALID_ROW) ? 16u : 0u;
    uint32_t roc = (ro != INVALID_ROW) ? ro : 0u;
    const __nv_bfloat16* sah = Ahi + roc + k0 + ahalf * 16;
    const __nv_bfloat16* sal = Alo + roc + k0 + ahalf * 16;
    uint32_t dahh = st + ST_AHI + ar * (PA * 2) + ahalf * 32;
    uint32_t dall = st + ST_ALO + ar * (PA * 2) + ahalf * 32;
    cp16(dahh,      sah,     sz);
    cp16(dahh + 16, sah + 8, sz);
    cp16(dall,      sal,     sz);
    cp16(dall + 16, sal + 8, sz);

    // B: 32 k-rows x 128 n; thread -> (krow = tid>>3, 32B-seg = tid&7)
    const int br = tid >> 3, bseg = tid & 7;
    const __nv_bfloat16* sbh = Bhi + (size_t)(k0 + br) * ldb + n0 + bseg * 16;
    const __nv_bfloat16* sbl = Blo + (size_t)(k0 + br) * ldb + n0 + bseg * 16;
    uint32_t dbh = st + ST_BHI + br * (PB * 2) + bseg * 32;
    uint32_t dbl = st + ST_BLO + br * (PB * 2) + bseg * 32;
    cp16(dbh,      sbh,     16u);
    cp16(dbh + 16, sbh + 8, 16u);
    cp16(dbl,      sbl,     16u);
    cp16(dbl + 16, sbl + 8, 16u);
}

// ---------------- compute one KC=32 chunk (bf16x3) ----------------
__device__ __forceinline__ void compute_chunk(
    uint32_t aHi, uint32_t aLo, uint32_t bHi, uint32_t bLo, float (&acc)[4][4][4])
{
#pragma unroll
    for (int ks = 0; ks < 2; ks++) {
        uint32_t ah[4][4], al[4][4], bh[2][4], bl[2][4];
#pragma unroll
        for (int mi = 0; mi < 4; mi++) {
            ldsm_x4(ah[mi], aHi + ks * 32 + mi * (16 * PA * 2));
            ldsm_x4(al[mi], aLo + ks * 32 + mi * (16 * PA * 2));
        }
#pragma unroll
        for (int nj = 0; nj < 2; nj++) {
            ldsm_x4t(bh[nj], bHi + ks * (16 * PB * 2) + nj * 32);
            ldsm_x4t(bl[nj], bLo + ks * (16 * PB * 2) + nj * 32);
        }
#pragma unroll
        for (int mi = 0; mi < 4; mi++)
#pragma unroll
            for (int nj = 0; nj < 2; nj++)
#pragma unroll
                for (int h = 0; h < 2; h++) {
                    int ni = nj * 2 + h;
                    mma_bf16(acc[mi][ni], ah[mi], bh[nj][h * 2], bh[nj][h * 2 + 1]);
                    mma_bf16(acc[mi][ni], ah[mi], bl[nj][h * 2], bl[nj][h * 2 + 1]);
                    mma_bf16(acc[mi][ni], al[mi], bh[nj][h * 2], bh[nj][h * 2 + 1]);
                }
    }
}

// ---------------- shared mainloop ----------------
__device__ __forceinline__ void mainloop(
    char* dsm, const __nv_bfloat16* Ahi, const __nv_bfloat16* Alo,
    const __nv_bfloat16* Bhi, const __nv_bfloat16* Blo,
    int ldb, int n0, int nch, float (&acc)[4][4][4])
{
    const int tid = threadIdx.x;
    const uint32_t sb = smem_u32(dsm);
    const uint32_t* rowoff = (const uint32_t*)dsm;

    const int lane = tid & 31, w = tid >> 5;
    const int m_warp = (w >> 2) * 64, n_warp = (w & 3) * 32;
    const int g = lane >> 3, r = lane & 7;
    const uint32_t a_lane = (uint32_t)(((m_warp + (g & 1) * 8 + r) * PA + (g >> 1) * 8) * 2);
    const uint32_t b_lane = (uint32_t)((((g & 1) * 8 + r) * PB + n_warp + (g >> 1) * 8) * 2);

    uint32_t stg[NSTG];
#pragma unroll
    for (int s = 0; s < NSTG; s++) stg[s] = sb + SM_HDR + s * ST_BYTES;

    issue_chunk(stg[0], Ahi, Alo, rowoff, Bhi, Blo, ldb, n0, 0, tid);
    CP_COMMIT();
    issue_chunk(stg[1], Ahi, Alo, rowoff, Bhi, Blo, ldb, n0, KC, tid);
    CP_COMMIT();

    for (int c = 0; c < nch; c++) {
        if (c + 2 < nch)
            issue_chunk(stg[(c + 2) % NSTG], Ahi, Alo, rowoff, Bhi, Blo,
                        ldb, n0, (c + 2) * KC, tid);
        CP_COMMIT();
        CP_WAIT2();
        __syncthreads();
        uint32_t st = stg[c % NSTG];
        compute_chunk(st + ST_AHI + a_lane, st + ST_ALO + a_lane,
                      st + ST_BHI + b_lane, st + ST_BLO + b_lane, acc);
        __syncthreads();
    }
}

// ---------------- conversion: fp32 -> bf16 hi/lo ----------------
__global__ void k_conv(const float4* __restrict__ src, uint2* __restrict__ hi,
                       uint2* __restrict__ lo, int n4) {
    int i = blockIdx.x * blockDim.x + threadIdx.x;
    if (i < n4) {
        uint2 h, l;
        split_pack(src[i], h, l);
        hi[i] = h;
        lo[i] = l;
    }
}

// ---------------- init / zero / gating / routing ----------------
__global__ void k_init() { if (threadIdx.x < NE) g_cnt[threadIdx.x] = 0; }

__global__ void k_zero_out(float* __restrict__ out) {
    size_t i = (size_t)blockIdx.x * blockDim.x + threadIdx.x;
    if (i < (size_t)T_TOK * DM / 4)
        reinterpret_cast<float4*>(out)[i] = make_float4(0.f, 0.f, 0.f, 0.f);
}

__global__ void k_gate(const float* __restrict__ x, const float* __restrict__ Wg,
                       const float* __restrict__ bg, float* __restrict__ out_logits) {
    int warp = threadIdx.x >> 5, lane = threadIdx.x & 31;
    int t = blockIdx.x * 8 + warp;
    if (t >= T_TOK) return;
    const float* xr = x + (size_t)t * DM;
    float acc[NE];
#pragma unroll
    for (int e = 0; e < NE; e++) acc[e] = 0.f;
    for (int k = lane; k < DM; k += 32) {
        float xv = xr[k];
        const float* w = Wg + (size_t)k * NE;
#pragma unroll
        for (int e = 0; e < NE; e++) acc[e] += xv * w[e];
    }
#pragma unroll
    for (int e = 0; e < NE; e++)
#pragma unroll
        for (int o = 16; o; o >>= 1) acc[e] += __shfl_xor_sync(0xffffffffu, acc[e], o);
    if (lane == 0) {
#pragma unroll
        for (int e = 0; e < NE; e++) {
            acc[e] += bg[e];
            out_logits[(size_t)t * NE + e] = acc[e];
        }
        int b0 = 0;
#pragma unroll
        for (int e = 1; e < NE; e++) if (acc[e] > acc[b0]) b0 = e;
        int b1 = (b0 == 0) ? 1 : 0;
#pragma unroll
        for (int e = 0; e < NE; e++) if (e != b0 && acc[e] > acc[b1]) b1 = e;
        float ex = expf(acc[b1] - acc[b0]);
        float w0 = 1.f / (1.f + ex);
        float w1 = ex * w0;
        g_eid[2 * t] = b0;     g_ew[2 * t] = w0;
        g_eid[2 * t + 1] = b1; g_ew[2 * t + 1] = w1;
        atomicAdd(&g_cnt[b0], 1);
        atomicAdd(&g_cnt[b1], 1);
    }
}

__global__ void k_offsets() {
    if (threadIdx.x == 0) {
        int s = 0;
#pragma unroll
        for (int e = 0; e < NE; e++) { g_off[e] = s; g_cur[e] = s; s += g_cnt[e]; }
    }
}

__global__ void k_scatter() {
    int a = blockIdx.x * blockDim.x + threadIdx.x;
    if (a < NASSIGN) {
        int e = g_eid[a];
        int pos = atomicAdd(&g_cur[e], 1);
        g_tok[pos] = a >> 1;
        g_wgt[pos] = g_ew[a];
    }
}

// ---------------- GEMM1: H(bf16 hi/lo) = relu(x @ W1[e] + b1[e]) ----------------
__global__ void __launch_bounds__(256, 1)
k_gemm1_mma(const float* __restrict__ b1) {
    extern __shared__ char dsm[];
    const int e = blockIdx.z;
    const int cnt = g_cnt[e];
    const int m0 = blockIdx.y * 128;
    if (m0 >= cnt) return;
    const int off = g_off[e];
    const int n0 = blockIdx.x * 128;
    const int tid = threadIdx.x;

    uint32_t* rowoff = (uint32_t*)dsm;
    if (tid < 128) {
        int gi = m0 + tid;
        rowoff[tid] = (gi < cnt) ? (uint32_t)(g_tok[off + gi] * DM) : INVALID_ROW;
    }
    __syncthreads();

    float acc[4][4][4];
#pragma unroll
    for (int a = 0; a < 4; a++)
#pragma unroll
        for (int b = 0; b < 4; b++)
#pragma unroll
            for (int c = 0; c < 4; c++) acc[a][b][c] = 0.f;

    mainloop(dsm, g_xhi, g_xlo,
             g_W1hi + (size_t)e * DM * DH, g_W1lo + (size_t)e * DM * DH,
             DH, n0, DM / KC, acc);

    const int lane = tid & 31, w = tid >> 5;
    const int m_warp = (w >> 2) * 64, n_warp = (w & 3) * 32;
    const float* bb = b1 + (size_t)e * DH;
#pragma unroll
    for (int mi = 0; mi < 4; mi++) {
#pragma unroll
        for (int ni = 0; ni < 4; ni++) {
            int col = n0 + n_warp + ni * 8 + (lane & 3) * 2;
            float bc0 = bb[col], bc1 = bb[col + 1];
#pragma unroll
            for (int hr = 0; hr < 2; hr++) {
                int lr = m_warp + mi * 16 + (lane >> 2) + hr * 8;
                int gi = m0 + lr;
                if (gi < cnt) {
                    float h0 = fmaxf(acc[mi][ni][hr * 2 + 0] + bc0, 0.f);
                    float h1 = fmaxf(acc[mi][ni][hr * 2 + 1] + bc1, 0.f);
                    __nv_bfloat16 h0h = __float2bfloat16(h0);
                    __nv_bfloat16 h1h = __float2bfloat16(h1);
                    __nv_bfloat16 h0l = __float2bfloat16(h0 - __bfloat162float(h0h));
                    __nv_bfloat16 h1l = __float2bfloat16(h1 - __bfloat162float(h1h));
                    size_t base = (size_t)(off + gi) * DH + col;
                    *(__nv_bfloat162*)(g_Hhi + base) = __halves2bfloat162(h0h, h1h);
                    *(__nv_bfloat162*)(g_Hlo + base) = __halves2bfloat162(h0l, h1l);
                }
            }
        }
    }
}

// ---------------- GEMM2: out[tok] += w * (H @ W2[e] + b2[e]) ----------------
__global__ void __launch_bounds__(256, 1)
k_gemm2_mma(const float* __restrict__ b2, float* __restrict__ out) {
    extern __shared__ char dsm[];
    const int e = blockIdx.z;
    const int cnt = g_cnt[e];
    const int m0 = blockIdx.y * 128;
    if (m0 >= cnt) return;
    const int off = g_off[e];
    const int n0 = blockIdx.x * 128;
    const int tid = threadIdx.x;

    uint32_t* rowoff = (uint32_t*)dsm;
    int* toks = (int*)(dsm + 512);
    float* wgts = (float*)(dsm + 1024);
    if (tid < 128) {
        int gi = m0 + tid;
        bool v = gi < cnt;
        rowoff[tid] = v ? (uint32_t)((off + gi) * DH) : INVALID_ROW;
        toks[tid] = v ? g_tok[off + gi] : 0;
        wgts[tid] = v ? g_wgt[off + gi] : 0.f;
    }
    __syncthreads();

    float acc[4][4][4];
#pragma unroll
    for (int a = 0; a < 4; a++)
#pragma unroll
        for (int b = 0; b < 4; b++)
#pragma unroll
            for (int c = 0; c < 4; c++) acc[a][b][c] = 0.f;

    mainloop(dsm, g_Hhi, g_Hlo,
             g_W2hi + (size_t)e * DH * DM, g_W2lo + (size_t)e * DH * DM,
             DM, n0, DH / KC, acc);

    const int lane = tid & 31, w = tid >> 5;
    const int m_warp = (w >> 2) * 64, n_warp = (w & 3) * 32;
    const float* bb = b2 + (size_t)e * DM;
#pragma unroll
    for (int mi = 0; mi < 4; mi++) {
#pragma unroll
        for (int ni = 0; ni < 4; ni++) {
            int col = n0 + n_warp + ni * 8 + (lane & 3) * 2;
            float bc0 = bb[col], bc1 = bb[col + 1];
#pragma unroll
            for (int hr = 0; hr < 2; hr++) {
                int lr = m_warp + mi * 16 + (lane >> 2) + hr * 8;
                int gi = m0 + lr;
                if (gi < cnt) {
                    int tok  = toks[lr];
                    float wv = wgts[lr];
                    float* orow = out + (size_t)tok * DM + col;
                    atomicAdd(orow,     wv * (acc[mi][ni][hr * 2 + 0] + bc0));
                    atomicAdd(orow + 1, wv * (acc[mi][ni][hr * 2 + 1] + bc1));
                }
            }
        }
    }
}

// ---------------- launch ----------------
extern "C" void kernel_launch(void* const* d_in, const int* in_sizes, int n_in,
                              void* d_out, int out_size) {
    const float* x  = (const float*)d_in[0];
    const float* Wg = (const float*)d_in[1];
    const float* bg = (const float*)d_in[2];
    const float* W1 = (const float*)d_in[3];
    const float* b1 = (const float*)d_in[4];
    const float* W2 = (const float*)d_in[5];
    const float* b2 = (const float*)d_in[6];
    float* out = (float*)d_out;

    cudaFuncSetAttribute(k_gemm1_mma, cudaFuncAttributeMaxDynamicSharedMemorySize, SMEM_TOTAL);
    cudaFuncSetAttribute(k_gemm2_mma, cudaFuncAttributeMaxDynamicSharedMemorySize, SMEM_TOTAL);

    // Resolve DEVICE addresses of __device__ symbols (host-side symbol names are
    // shadow handles, NOT device pointers — the R5 bug).
    void *p_xhi, *p_xlo, *p_w1hi, *p_w1lo, *p_w2hi, *p_w2lo;
    cudaGetSymbolAddress(&p_xhi,  g_xhi);
    cudaGetSymbolAddress(&p_xlo,  g_xlo);
    cudaGetSymbolAddress(&p_w1hi, g_W1hi);
    cudaGetSymbolAddress(&p_w1lo, g_W1lo);
    cudaGetSymbolAddress(&p_w2hi, g_W2hi);
    cudaGetSymbolAddress(&p_w2lo, g_W2lo);

    k_init<<<1, 32>>>();
    k_zero_out<<<(T_TOK * DM / 4 + 255) / 256, 256>>>(out);
    k_gate<<<T_TOK / 8, 256>>>(x, Wg, bg, out + (size_t)T_TOK * DM);
    k_offsets<<<1, 32>>>();
    k_scatter<<<(NASSIGN + 255) / 256, 256>>>();

    // conversions (independent of routing)
    {
        int n4x = T_TOK * DM / 4;
        k_conv<<<(n4x + 255) / 256, 256>>>((const float4*)x, (uint2*)p_xhi, (uint2*)p_xlo, n4x);
        int n4w = NE * DM * DH / 4;
        k_conv<<<(n4w + 255) / 256, 256>>>((const float4*)W1, (uint2*)p_w1hi, (uint2*)p_w1lo, n4w);
        k_conv<<<(n4w + 255) / 256, 256>>>((const float4*)W2, (uint2*)p_w2hi, (uint2*)p_w2lo, n4w);
    }

    k_gemm1_mma<<<dim3(DH / 128, T_TOK / 128, NE), 256, SMEM_TOTAL>>>(b1);
    k_gemm2_mma<<<dim3(DM / 128, T_TOK / 128, NE), 256, SMEM_TOTAL>>>(b2, out);
}

// round 7
// speedup vs baseline: 2.5336x; 1.2069x over previous
#include <cuda_runtime.h>
#include <cuda_bf16.h>
#include <cstdint>
#include <math.h>

#define T_TOK    4096
#define DM       1024
#define DH       4096
#define NE       8
#define NASSIGN  (T_TOK * 2)

#define KC    32
#define PA    40           // A smem pitch (bf16): 32 + 8 pad
#define PB    136          // B smem pitch (bf16): 128 + 8 pad
#define NSTG  4

#define ST_AHI   0
#define ST_ALO   10240     // 128*PA*2
#define ST_BHI   20480
#define ST_BLO   29184     // +32*PB*2
#define ST_BYTES 37888
#define SM_HDR   2048
#define SMEM_TOTAL (SM_HDR + NSTG * ST_BYTES)   // 153600

#define INVALID_ROW 0xFFFFFFFFu
#define N4X (T_TOK * DM / 4)
#define N4W (NE * DM * DH / 4)

// ---------------- static device scratch ----------------
__device__ __nv_bfloat16 g_xhi[(size_t)T_TOK * DM];
__device__ __nv_bfloat16 g_xlo[(size_t)T_TOK * DM];
__device__ __nv_bfloat16 g_W1hi[(size_t)NE * DM * DH];
__device__ __nv_bfloat16 g_W1lo[(size_t)NE * DM * DH];
__device__ __nv_bfloat16 g_W2hi[(size_t)NE * DH * DM];
__device__ __nv_bfloat16 g_W2lo[(size_t)NE * DH * DM];
__device__ __nv_bfloat16 g_Hhi[(size_t)NASSIGN * DH];
__device__ __nv_bfloat16 g_Hlo[(size_t)NASSIGN * DH];
__device__ int   g_tok[NASSIGN];
__device__ float g_wgt[NASSIGN];
__device__ int   g_eid[NASSIGN];
__device__ float g_ew [NASSIGN];
__device__ int   g_cnt[NE];
__device__ int   g_off[NE];

// ---------------- helpers ----------------
__device__ __forceinline__ uint32_t smem_u32(const void* p) {
    uint32_t a;
    asm("{ .reg .u64 t; cvta.to.shared.u64 t, %1; cvt.u32.u64 %0, t; }" : "=r"(a) : "l"(p));
    return a;
}
__device__ __forceinline__ void split_pack(float4 v, uint2& hi, uint2& lo) {
    __nv_bfloat16 hx = __float2bfloat16(v.x), hy = __float2bfloat16(v.y);
    __nv_bfloat16 hz = __float2bfloat16(v.z), hw = __float2bfloat16(v.w);
    __nv_bfloat16 lx = __float2bfloat16(v.x - __bfloat162float(hx));
    __nv_bfloat16 ly = __float2bfloat16(v.y - __bfloat162float(hy));
    __nv_bfloat16 lz = __float2bfloat16(v.z - __bfloat162float(hz));
    __nv_bfloat16 lw = __float2bfloat16(v.w - __bfloat162float(hw));
    __nv_bfloat162 h01 = __halves2bfloat162(hx, hy), h23 = __halves2bfloat162(hz, hw);
    __nv_bfloat162 l01 = __halves2bfloat162(lx, ly), l23 = __halves2bfloat162(lz, lw);
    hi.x = *(uint32_t*)&h01; hi.y = *(uint32_t*)&h23;
    lo.x = *(uint32_t*)&l01; lo.y = *(uint32_t*)&l23;
}
__device__ __forceinline__ void ldsm_x4(uint32_t (&d)[4], uint32_t addr) {
    asm volatile("ldmatrix.sync.aligned.m8n8.x4.shared.b16 {%0,%1,%2,%3}, [%4];"
        : "=r"(d[0]), "=r"(d[1]), "=r"(d[2]), "=r"(d[3]) : "r"(addr));
}
__device__ __forceinline__ void ldsm_x4t(uint32_t (&d)[4], uint32_t addr) {
    asm volatile("ldmatrix.sync.aligned.m8n8.x4.trans.shared.b16 {%0,%1,%2,%3}, [%4];"
        : "=r"(d[0]), "=r"(d[1]), "=r"(d[2]), "=r"(d[3]) : "r"(addr));
}
__device__ __forceinline__ void mma_bf16(float (&d)[4], const uint32_t (&a)[4],
                                          uint32_t b0, uint32_t b1) {
    asm volatile("mma.sync.aligned.m16n8k16.row.col.f32.bf16.bf16.f32 "
        "{%0,%1,%2,%3},{%4,%5,%6,%7},{%8,%9},{%0,%1,%2,%3};"
        : "+f"(d[0]), "+f"(d[1]), "+f"(d[2]), "+f"(d[3])
        : "r"(a[0]), "r"(a[1]), "r"(a[2]), "r"(a[3]), "r"(b0), "r"(b1));
}
__device__ __forceinline__ void cp16(uint32_t dst, const void* src, uint32_t sz) {
    asm volatile("cp.async.cg.shared.global [%0], [%1], 16, %2;"
                 :: "r"(dst), "l"(src), "r"(sz));
}
#define CP_COMMIT() asm volatile("cp.async.commit_group;" ::: "memory")
#define CP_WAIT2()  asm volatile("cp.async.wait_group 2;" ::: "memory")

// ---------------- issue one KC=32 chunk via cp.async (512 threads) ----------------
__device__ __forceinline__ void issue_chunk(
    uint32_t st, const __nv_bfloat16* __restrict__ Ahi, const __nv_bfloat16* __restrict__ Alo,
    const uint32_t* __restrict__ rowoff,
    const __nv_bfloat16* __restrict__ Bhi, const __nv_bfloat16* __restrict__ Blo,
    int ldb, int n0, int k0, int tid)
{
    // A: 128 rows x 32 k; thread -> (row = tid>>2, 16B-quarter = tid&3)
    const int ar = tid >> 2, aq = tid & 3;
    uint32_t ro = rowoff[ar];
    uint32_t sz = (ro != INVALID_ROW) ? 16u : 0u;
    uint32_t roc = (ro != INVALID_ROW) ? ro : 0u;
    const __nv_bfloat16* sah = Ahi + roc + k0 + aq * 8;
    const __nv_bfloat16* sal = Alo + roc + k0 + aq * 8;
    cp16(st + ST_AHI + ar * (PA * 2) + aq * 16, sah, sz);
    cp16(st + ST_ALO + ar * (PA * 2) + aq * 16, sal, sz);

    // B: 32 k-rows x 128 n; thread -> (krow = tid>>4, 16B-seg = tid&15)
    const int br = tid >> 4, bs = tid & 15;
    const __nv_bfloat16* sbh = Bhi + (size_t)(k0 + br) * ldb + n0 + bs * 8;
    const __nv_bfloat16* sbl = Blo + (size_t)(k0 + br) * ldb + n0 + bs * 8;
    cp16(st + ST_BHI + br * (PB * 2) + bs * 16, sbh, 16u);
    cp16(st + ST_BLO + br * (PB * 2) + bs * 16, sbl, 16u);
}

// ---------------- compute one KC=32 chunk (bf16x3), warp tile 32x32 ----------------
__device__ __forceinline__ void compute_chunk(
    uint32_t aHi, uint32_t aLo, uint32_t bHi, uint32_t bLo, float (&acc)[2][4][4])
{
#pragma unroll
    for (int ks = 0; ks < 2; ks++) {
        uint32_t ah[2][4], al[2][4], bh[2][4], bl[2][4];
#pragma unroll
        for (int mi = 0; mi < 2; mi++) {
            ldsm_x4(ah[mi], aHi + ks * 32 + mi * (16 * PA * 2));
            ldsm_x4(al[mi], aLo + ks * 32 + mi * (16 * PA * 2));
        }
#pragma unroll
        for (int nj = 0; nj < 2; nj++) {
            ldsm_x4t(bh[nj], bHi + ks * (16 * PB * 2) + nj * 32);
            ldsm_x4t(bl[nj], bLo + ks * (16 * PB * 2) + nj * 32);
        }
#pragma unroll
        for (int mi = 0; mi < 2; mi++)
#pragma unroll
            for (int nj = 0; nj < 2; nj++)
#pragma unroll
                for (int h = 0; h < 2; h++) {
                    int ni = nj * 2 + h;
                    mma_bf16(acc[mi][ni], ah[mi], bh[nj][h * 2], bh[nj][h * 2 + 1]);
                    mma_bf16(acc[mi][ni], ah[mi], bl[nj][h * 2], bl[nj][h * 2 + 1]);
                    mma_bf16(acc[mi][ni], al[mi], bh[nj][h * 2], bh[nj][h * 2 + 1]);
                }
    }
}

// ---------------- shared mainloop (512 threads, 16 warps) ----------------
__device__ __forceinline__ void mainloop(
    char* dsm, const __nv_bfloat16* Ahi, const __nv_bfloat16* Alo,
    const __nv_bfloat16* Bhi, const __nv_bfloat16* Blo,
    int ldb, int n0, int nch, float (&acc)[2][4][4])
{
    const int tid = threadIdx.x;
    const uint32_t sb = smem_u32(dsm);
    const uint32_t* rowoff = (const uint32_t*)dsm;

    const int lane = tid & 31, w = tid >> 5;
    const int m_warp = (w >> 2) * 32, n_warp = (w & 3) * 32;
    const int g = lane >> 3, r = lane & 7;
    const uint32_t a_lane = (uint32_t)(((m_warp + (g & 1) * 8 + r) * PA + (g >> 1) * 8) * 2);
    const uint32_t b_lane = (uint32_t)((((g & 1) * 8 + r) * PB + n_warp + (g >> 1) * 8) * 2);

    uint32_t stg[NSTG];
#pragma unroll
    for (int s = 0; s < NSTG; s++) stg[s] = sb + SM_HDR + s * ST_BYTES;

    issue_chunk(stg[0], Ahi, Alo, rowoff, Bhi, Blo, ldb, n0, 0, tid);
    CP_COMMIT();
    issue_chunk(stg[1], Ahi, Alo, rowoff, Bhi, Blo, ldb, n0, KC, tid);
    CP_COMMIT();

    for (int c = 0; c < nch; c++) {
        if (c + 2 < nch)
            issue_chunk(stg[(c + 2) & 3], Ahi, Alo, rowoff, Bhi, Blo,
                        ldb, n0, (c + 2) * KC, tid);
        CP_COMMIT();
        CP_WAIT2();
        __syncthreads();
        uint32_t st = stg[c & 3];
        compute_chunk(st + ST_AHI + a_lane, st + ST_ALO + a_lane,
                      st + ST_BHI + b_lane, st + ST_BLO + b_lane, acc);
    }
}

// ---------------- fused conversion: x, W1, W2 -> bf16 hi/lo ----------------
__global__ void k_conv_all(const float4* __restrict__ x, const float4* __restrict__ W1,
                           const float4* __restrict__ W2,
                           uint2* __restrict__ xhi, uint2* __restrict__ xlo,
                           uint2* __restrict__ w1hi, uint2* __restrict__ w1lo,
                           uint2* __restrict__ w2hi, uint2* __restrict__ w2lo) {
    int i = blockIdx.x * blockDim.x + threadIdx.x;
    uint2 h, l;
    if (i < N4X) {
        split_pack(x[i], h, l); xhi[i] = h; xlo[i] = l;
    } else if (i < N4X + N4W) {
        int j = i - N4X;
        split_pack(W1[j], h, l); w1hi[j] = h; w1lo[j] = l;
    } else if (i < N4X + 2 * N4W) {
        int j = i - N4X - N4W;
        split_pack(W2[j], h, l); w2hi[j] = h; w2lo[j] = l;
    }
}

// ---------------- gating (+ output zeroing folded in) ----------------
__global__ void k_gate(const float* __restrict__ x, const float* __restrict__ Wg,
                       const float* __restrict__ bg, float* __restrict__ out) {
    // zero this block's slice of the main output [T_TOK*DM]
    {
        float4* o4 = (float4*)out;
        int base = blockIdx.x * 2048;   // 512 blocks * 2048 = 1M float4
#pragma unroll
        for (int i = 0; i < 8; i++)
            o4[base + i * 256 + threadIdx.x] = make_float4(0.f, 0.f, 0.f, 0.f);
    }
    float* out_logits = out + (size_t)T_TOK * DM;
    int warp = threadIdx.x >> 5, lane = threadIdx.x & 31;
    int t = blockIdx.x * 8 + warp;
    if (t >= T_TOK) return;
    const float* xr = x + (size_t)t * DM;
    float acc[NE];
#pragma unroll
    for (int e = 0; e < NE; e++) acc[e] = 0.f;
    for (int k = lane; k < DM; k += 32) {
        float xv = xr[k];
        const float* w = Wg + (size_t)k * NE;
#pragma unroll
        for (int e = 0; e < NE; e++) acc[e] += xv * w[e];
    }
#pragma unroll
    for (int e = 0; e < NE; e++)
#pragma unroll
        for (int o = 16; o; o >>= 1) acc[e] += __shfl_xor_sync(0xffffffffu, acc[e], o);
    if (lane == 0) {
#pragma unroll
        for (int e = 0; e < NE; e++) {
            acc[e] += bg[e];
            out_logits[(size_t)t * NE + e] = acc[e];
        }
        int b0 = 0;
#pragma unroll
        for (int e = 1; e < NE; e++) if (acc[e] > acc[b0]) b0 = e;
        int b1 = (b0 == 0) ? 1 : 0;
#pragma unroll
        for (int e = 0; e < NE; e++) if (e != b0 && acc[e] > acc[b1]) b1 = e;
        float ex = expf(acc[b1] - acc[b0]);
        float w0 = 1.f / (1.f + ex);
        float w1 = ex * w0;
        g_eid[2 * t] = b0;     g_ew[2 * t] = w0;
        g_eid[2 * t + 1] = b1; g_ew[2 * t + 1] = w1;
    }
}

// ---------------- routing: counts + offsets + scatter in one block ----------------
__global__ void k_route() {
    __shared__ int s_cnt[NE], s_off[NE], s_cur[NE];
    int tid = threadIdx.x;
    if (tid < NE) s_cnt[tid] = 0;
    __syncthreads();
    for (int a = tid; a < NASSIGN; a += blockDim.x)
        atomicAdd(&s_cnt[g_eid[a]], 1);
    __syncthreads();
    if (tid == 0) {
        int s = 0;
#pragma unroll
        for (int e = 0; e < NE; e++) {
            s_off[e] = s; s_cur[e] = s;
            g_cnt[e] = s_cnt[e]; g_off[e] = s;
            s += s_cnt[e];
        }
    }
    __syncthreads();
    for (int a = tid; a < NASSIGN; a += blockDim.x) {
        int e = g_eid[a];
        int pos = atomicAdd(&s_cur[e], 1);
        g_tok[pos] = a >> 1;
        g_wgt[pos] = g_ew[a];
    }
}

// ---------------- GEMM1: H(bf16 hi/lo) = relu(x @ W1[e] + b1[e]) ----------------
__global__ void __launch_bounds__(512, 1)
k_gemm1_mma(const float* __restrict__ b1) {
    extern __shared__ char dsm[];
    const int e = blockIdx.z;
    const int cnt = g_cnt[e];
    const int m0 = blockIdx.y * 128;
    if (m0 >= cnt) return;
    const int off = g_off[e];
    const int n0 = blockIdx.x * 128;
    const int tid = threadIdx.x;

    uint32_t* rowoff = (uint32_t*)dsm;
    if (tid < 128) {
        int gi = m0 + tid;
        rowoff[tid] = (gi < cnt) ? (uint32_t)(g_tok[off + gi] * DM) : INVALID_ROW;
    }
    __syncthreads();

    float acc[2][4][4];
#pragma unroll
    for (int a = 0; a < 2; a++)
#pragma unroll
        for (int b = 0; b < 4; b++)
#pragma unroll
            for (int c = 0; c < 4; c++) acc[a][b][c] = 0.f;

    mainloop(dsm, g_xhi, g_xlo,
             g_W1hi + (size_t)e * DM * DH, g_W1lo + (size_t)e * DM * DH,
             DH, n0, DM / KC, acc);

    const int lane = tid & 31, w = tid >> 5;
    const int m_warp = (w >> 2) * 32, n_warp = (w & 3) * 32;
    const float* bb = b1 + (size_t)e * DH;
#pragma unroll
    for (int mi = 0; mi < 2; mi++) {
#pragma unroll
        for (int ni = 0; ni < 4; ni++) {
            int col = n0 + n_warp + ni * 8 + (lane & 3) * 2;
            float bc0 = bb[col], bc1 = bb[col + 1];
#pragma unroll
            for (int hr = 0; hr < 2; hr++) {
                int lr = m_warp + mi * 16 + (lane >> 2) + hr * 8;
                int gi = m0 + lr;
                if (gi < cnt) {
                    float h0 = fmaxf(acc[mi][ni][hr * 2 + 0] + bc0, 0.f);
                    float h1 = fmaxf(acc[mi][ni][hr * 2 + 1] + bc1, 0.f);
                    __nv_bfloat16 h0h = __float2bfloat16(h0);
                    __nv_bfloat16 h1h = __float2bfloat16(h1);
                    __nv_bfloat16 h0l = __float2bfloat16(h0 - __bfloat162float(h0h));
                    __nv_bfloat16 h1l = __float2bfloat16(h1 - __bfloat162float(h1h));
                    size_t base = (size_t)(off + gi) * DH + col;
                    *(__nv_bfloat162*)(g_Hhi + base) = __halves2bfloat162(h0h, h1h);
                    *(__nv_bfloat162*)(g_Hlo + base) = __halves2bfloat162(h0l, h1l);
                }
            }
        }
    }
}

// ---------------- GEMM2 (K-split 2): out[tok] += w * (H @ W2[e] + b2[e]) ----------------
__global__ void __launch_bounds__(512, 1)
k_gemm2_mma(const float* __restrict__ b2, float* __restrict__ out) {
    extern __shared__ char dsm[];
    const int e = blockIdx.z >> 1;
    const int half = blockIdx.z & 1;
    const int cnt = g_cnt[e];
    const int m0 = blockIdx.y * 128;
    if (m0 >= cnt) return;
    const int off = g_off[e];
    const int n0 = blockIdx.x * 128;
    const int koff = half * (DH / 2);
    const int tid = threadIdx.x;

    uint32_t* rowoff = (uint32_t*)dsm;
    int* toks = (int*)(dsm + 512);
    float* wgts = (float*)(dsm + 1024);
    if (tid < 128) {
        int gi = m0 + tid;
        bool v = gi < cnt;
        rowoff[tid] = v ? (uint32_t)((off + gi) * DH + koff) : INVALID_ROW;
        toks[tid] = v ? g_tok[off + gi] : 0;
        wgts[tid] = v ? g_wgt[off + gi] : 0.f;
    }
    __syncthreads();

    float acc[2][4][4];
#pragma unroll
    for (int a = 0; a < 2; a++)
#pragma unroll
        for (int b = 0; b < 4; b++)
#pragma unroll
            for (int c = 0; c < 4; c++) acc[a][b][c] = 0.f;

    mainloop(dsm, g_Hhi, g_Hlo,
             g_W2hi + (size_t)e * DH * DM + (size_t)koff * DM,
             g_W2lo + (size_t)e * DH * DM + (size_t)koff * DM,
             DM, n0, (DH / 2) / KC, acc);

    const int lane = tid & 31, w = tid >> 5;
    const int m_warp = (w >> 2) * 32, n_warp = (w & 3) * 32;
    const float* bb = b2 + (size_t)e * DM;
#pragma unroll
    for (int mi = 0; mi < 2; mi++) {
#pragma unroll
        for (int ni = 0; ni < 4; ni++) {
            int col = n0 + n_warp + ni * 8 + (lane & 3) * 2;
            float bc0 = half ? 0.f : bb[col];
            float bc1 = half ? 0.f : bb[col + 1];
#pragma unroll
            for (int hr = 0; hr < 2; hr++) {
                int lr = m_warp + mi * 16 + (lane >> 2) + hr * 8;
                int gi = m0 + lr;
                if (gi < cnt) {
                    int tok  = toks[lr];
                    float wv = wgts[lr];
                    float* orow = out + (size_t)tok * DM + col;
                    atomicAdd(orow,     wv * (acc[mi][ni][hr * 2 + 0] + bc0));
                    atomicAdd(orow + 1, wv * (acc[mi][ni][hr * 2 + 1] + bc1));
                }
            }
        }
    }
}

// ---------------- launch ----------------
extern "C" void kernel_launch(void* const* d_in, const int* in_sizes, int n_in,
                              void* d_out, int out_size) {
    const float* x  = (const float*)d_in[0];
    const float* Wg = (const float*)d_in[1];
    const float* bg = (const float*)d_in[2];
    const float* W1 = (const float*)d_in[3];
    const float* b1 = (const float*)d_in[4];
    const float* W2 = (const float*)d_in[5];
    const float* b2 = (const float*)d_in[6];
    float* out = (float*)d_out;

    cudaFuncSetAttribute(k_gemm1_mma, cudaFuncAttributeMaxDynamicSharedMemorySize, SMEM_TOTAL);
    cudaFuncSetAttribute(k_gemm2_mma, cudaFuncAttributeMaxDynamicSharedMemorySize, SMEM_TOTAL);

    void *p_xhi, *p_xlo, *p_w1hi, *p_w1lo, *p_w2hi, *p_w2lo;
    cudaGetSymbolAddress(&p_xhi,  g_xhi);
    cudaGetSymbolAddress(&p_xlo,  g_xlo);
    cudaGetSymbolAddress(&p_w1hi, g_W1hi);
    cudaGetSymbolAddress(&p_w1lo, g_W1lo);
    cudaGetSymbolAddress(&p_w2hi, g_W2hi);
    cudaGetSymbolAddress(&p_w2lo, g_W2lo);

    // 1: conversions (independent)
    {
        int total = N4X + 2 * N4W;
        k_conv_all<<<(total + 255) / 256, 256>>>(
            (const float4*)x, (const float4*)W1, (const float4*)W2,
            (uint2*)p_xhi, (uint2*)p_xlo, (uint2*)p_w1hi, (uint2*)p_w1lo,
            (uint2*)p_w2hi, (uint2*)p_w2lo);
    }
    // 2: gating + output zeroing
    k_gate<<<T_TOK / 8, 256>>>(x, Wg, bg, out);
    // 3: routing (single block)
    k_route<<<1, 1024>>>();
    // 4: GEMM1 (profiled launch)
    k_gemm1_mma<<<dim3(DH / 128, T_TOK / 128, NE), 512, SMEM_TOTAL>>>(b1);
    // 5: GEMM2, K-split 2
    k_gemm2_mma<<<dim3(DM / 128, T_TOK / 128, NE * 2), 512, SMEM_TOTAL>>>(b2, out);
}

// round 8
// speedup vs baseline: 2.8698x; 1.1327x over previous
#include <cuda_runtime.h>
#include <cuda_bf16.h>
#include <cstdint>
#include <math.h>

#define T_TOK    4096
#define DM       1024
#define DH       4096
#define NE       8
#define NASSIGN  (T_TOK * 2)

#define KC    32
#define PA    40           // A smem pitch (bf16): 32 + 8 pad
#define PB    264          // B smem pitch (bf16): 256 + 8 pad
#define NSTG  4

// stage layout (bytes)
#define ST_AHI   0
#define ST_ALO   10240     // 128*PA*2 = 10240
#define ST_BHI   20480
#define ST_BLO   37376     // +32*PB*2 = 16896
#define ST_BYTES 54272
#define SM_HDR   2048
#define SMEM_TOTAL (SM_HDR + NSTG * ST_BYTES)   // 219136

#define INVALID_ROW 0xFFFFFFFFu
#define N4X (T_TOK * DM / 4)
#define N4W (NE * DM * DH / 4)

// ---------------- static device scratch ----------------
__device__ __nv_bfloat16 g_xhi[(size_t)T_TOK * DM];
__device__ __nv_bfloat16 g_xlo[(size_t)T_TOK * DM];
__device__ __nv_bfloat16 g_W1hi[(size_t)NE * DM * DH];
__device__ __nv_bfloat16 g_W1lo[(size_t)NE * DM * DH];
__device__ __nv_bfloat16 g_W2hi[(size_t)NE * DH * DM];
__device__ __nv_bfloat16 g_W2lo[(size_t)NE * DH * DM];
__device__ __nv_bfloat16 g_Hhi[(size_t)NASSIGN * DH];
__device__ __nv_bfloat16 g_Hlo[(size_t)NASSIGN * DH];
__device__ int   g_tok[NASSIGN];
__device__ float g_wgt[NASSIGN];
__device__ int   g_eid[NASSIGN];
__device__ float g_ew [NASSIGN];
__device__ int   g_cnt[NE];
__device__ int   g_off[NE];

// ---------------- helpers ----------------
__device__ __forceinline__ uint32_t smem_u32(const void* p) {
    uint32_t a;
    asm("{ .reg .u64 t; cvta.to.shared.u64 t, %1; cvt.u32.u64 %0, t; }" : "=r"(a) : "l"(p));
    return a;
}
__device__ __forceinline__ void split_pack(float4 v, uint2& hi, uint2& lo) {
    __nv_bfloat16 hx = __float2bfloat16(v.x), hy = __float2bfloat16(v.y);
    __nv_bfloat16 hz = __float2bfloat16(v.z), hw = __float2bfloat16(v.w);
    __nv_bfloat16 lx = __float2bfloat16(v.x - __bfloat162float(hx));
    __nv_bfloat16 ly = __float2bfloat16(v.y - __bfloat162float(hy));
    __nv_bfloat16 lz = __float2bfloat16(v.z - __bfloat162float(hz));
    __nv_bfloat16 lw = __float2bfloat16(v.w - __bfloat162float(hw));
    __nv_bfloat162 h01 = __halves2bfloat162(hx, hy), h23 = __halves2bfloat162(hz, hw);
    __nv_bfloat162 l01 = __halves2bfloat162(lx, ly), l23 = __halves2bfloat162(lz, lw);
    hi.x = *(uint32_t*)&h01; hi.y = *(uint32_t*)&h23;
    lo.x = *(uint32_t*)&l01; lo.y = *(uint32_t*)&l23;
}
__device__ __forceinline__ void ldsm_x4(uint32_t (&d)[4], uint32_t addr) {
    asm volatile("ldmatrix.sync.aligned.m8n8.x4.shared.b16 {%0,%1,%2,%3}, [%4];"
        : "=r"(d[0]), "=r"(d[1]), "=r"(d[2]), "=r"(d[3]) : "r"(addr));
}
__device__ __forceinline__ void ldsm_x4t(uint32_t (&d)[4], uint32_t addr) {
    asm volatile("ldmatrix.sync.aligned.m8n8.x4.trans.shared.b16 {%0,%1,%2,%3}, [%4];"
        : "=r"(d[0]), "=r"(d[1]), "=r"(d[2]), "=r"(d[3]) : "r"(addr));
}
__device__ __forceinline__ void mma_bf16(float (&d)[4], const uint32_t (&a)[4],
                                          uint32_t b0, uint32_t b1) {
    asm volatile("mma.sync.aligned.m16n8k16.row.col.f32.bf16.bf16.f32 "
        "{%0,%1,%2,%3},{%4,%5,%6,%7},{%8,%9},{%0,%1,%2,%3};"
        : "+f"(d[0]), "+f"(d[1]), "+f"(d[2]), "+f"(d[3])
        : "r"(a[0]), "r"(a[1]), "r"(a[2]), "r"(a[3]), "r"(b0), "r"(b1));
}
__device__ __forceinline__ void cp16(uint32_t dst, const void* src, uint32_t sz) {
    asm volatile("cp.async.cg.shared.global [%0], [%1], 16, %2;"
                 :: "r"(dst), "l"(src), "r"(sz));
}
#define CP_COMMIT() asm volatile("cp.async.commit_group;" ::: "memory")
#define CP_WAIT2()  asm volatile("cp.async.wait_group 2;" ::: "memory")

// ---------------- issue one KC=32 x (128 A-rows, 256 B-cols) chunk ----------------
__device__ __forceinline__ void issue_chunk(
    uint32_t st, const __nv_bfloat16* __restrict__ Ahi, const __nv_bfloat16* __restrict__ Alo,
    const uint32_t* __restrict__ rowoff,
    const __nv_bfloat16* __restrict__ Bhi, const __nv_bfloat16* __restrict__ Blo,
    int ldb, int n0, int k0, int tid)
{
    // A: 128 rows x 32 k; thread -> (row = tid>>2, 16B-quarter = tid&3)
    const int ar = tid >> 2, aq = tid & 3;
    uint32_t ro = rowoff[ar];
    uint32_t sz = (ro != INVALID_ROW) ? 16u : 0u;
    uint32_t roc = (ro != INVALID_ROW) ? ro : 0u;
    cp16(st + ST_AHI + ar * (PA * 2) + aq * 16, Ahi + roc + k0 + aq * 8, sz);
    cp16(st + ST_ALO + ar * (PA * 2) + aq * 16, Alo + roc + k0 + aq * 8, sz);

    // B: 32 k-rows x 256 n; thread -> (krow = tid>>4, 2 x 16B segs: tid&15, +16)
    const int br = tid >> 4, bs = tid & 15;
    const __nv_bfloat16* sbh = Bhi + (size_t)(k0 + br) * ldb + n0;
    const __nv_bfloat16* sbl = Blo + (size_t)(k0 + br) * ldb + n0;
    uint32_t dbh = st + ST_BHI + br * (PB * 2);
    uint32_t dbl = st + ST_BLO + br * (PB * 2);
    cp16(dbh + bs * 16,         sbh + bs * 8,         16u);
    cp16(dbh + (bs + 16) * 16,  sbh + (bs + 16) * 8,  16u);
    cp16(dbl + bs * 16,         sbl + bs * 8,         16u);
    cp16(dbl + (bs + 16) * 16,  sbl + (bs + 16) * 8,  16u);
}

// ---------------- compute one chunk (bf16x3), warp tile 32x64 ----------------
__device__ __forceinline__ void compute_chunk(
    uint32_t aHi, uint32_t aLo, uint32_t bHi, uint32_t bLo, float (&acc)[2][8][4])
{
#pragma unroll
    for (int ks = 0; ks < 2; ks++) {
        uint32_t ah[2][4], al[2][4];
#pragma unroll
        for (int mi = 0; mi < 2; mi++) {
            ldsm_x4(ah[mi], aHi + ks * 32 + mi * (16 * PA * 2));
            ldsm_x4(al[mi], aLo + ks * 32 + mi * (16 * PA * 2));
        }
#pragma unroll
        for (int njp = 0; njp < 2; njp++) {           // two n32 halves of the n64 tile
            uint32_t bh[2][4], bl[2][4];
#pragma unroll
            for (int j = 0; j < 2; j++) {
                uint32_t boff = ks * (16 * PB * 2) + (njp * 2 + j) * 32;
                ldsm_x4t(bh[j], bHi + boff);
                ldsm_x4t(bl[j], bLo + boff);
            }
#pragma unroll
            for (int mi = 0; mi < 2; mi++)
#pragma unroll
                for (int j = 0; j < 2; j++)
#pragma unroll
                    for (int h = 0; h < 2; h++) {
                        int ni = njp * 4 + j * 2 + h;
                        mma_bf16(acc[mi][ni], ah[mi], bh[j][h * 2], bh[j][h * 2 + 1]);
                        mma_bf16(acc[mi][ni], ah[mi], bl[j][h * 2], bl[j][h * 2 + 1]);
                        mma_bf16(acc[mi][ni], al[mi], bh[j][h * 2], bh[j][h * 2 + 1]);
                    }
        }
    }
}

// ---------------- shared mainloop (512 threads, 16 warps, CTA 128x256) ----------------
__device__ __forceinline__ void mainloop(
    char* dsm, const __nv_bfloat16* Ahi, const __nv_bfloat16* Alo,
    const __nv_bfloat16* Bhi, const __nv_bfloat16* Blo,
    int ldb, int n0, int nch, float (&acc)[2][8][4])
{
    const int tid = threadIdx.x;
    const uint32_t sb = smem_u32(dsm);
    const uint32_t* rowoff = (const uint32_t*)dsm;

    const int lane = tid & 31, w = tid >> 5;
    const int m_warp = (w >> 2) * 32, n_warp = (w & 3) * 64;
    const int g = lane >> 3, r = lane & 7;
    const uint32_t a_lane = (uint32_t)(((m_warp + (g & 1) * 8 + r) * PA + (g >> 1) * 8) * 2);
    const uint32_t b_lane = (uint32_t)((((g & 1) * 8 + r) * PB + n_warp + (g >> 1) * 8) * 2);

    uint32_t stg[NSTG];
#pragma unroll
    for (int s = 0; s < NSTG; s++) stg[s] = sb + SM_HDR + s * ST_BYTES;

    issue_chunk(stg[0], Ahi, Alo, rowoff, Bhi, Blo, ldb, n0, 0, tid);
    CP_COMMIT();
    issue_chunk(stg[1], Ahi, Alo, rowoff, Bhi, Blo, ldb, n0, KC, tid);
    CP_COMMIT();

    for (int c = 0; c < nch; c++) {
        if (c + 2 < nch)
            issue_chunk(stg[(c + 2) & 3], Ahi, Alo, rowoff, Bhi, Blo,
                        ldb, n0, (c + 2) * KC, tid);
        CP_COMMIT();
        CP_WAIT2();
        __syncthreads();
        uint32_t st = stg[c & 3];
        compute_chunk(st + ST_AHI + a_lane, st + ST_ALO + a_lane,
                      st + ST_BHI + b_lane, st + ST_BLO + b_lane, acc);
    }
}

// ---------------- fused conversion: x, W1, W2 -> bf16 hi/lo ----------------
__global__ void k_conv_all(const float4* __restrict__ x, const float4* __restrict__ W1,
                           const float4* __restrict__ W2,
                           uint2* __restrict__ xhi, uint2* __restrict__ xlo,
                           uint2* __restrict__ w1hi, uint2* __restrict__ w1lo,
                           uint2* __restrict__ w2hi, uint2* __restrict__ w2lo) {
    int i = blockIdx.x * blockDim.x + threadIdx.x;
    uint2 h, l;
    if (i < N4X) {
        split_pack(x[i], h, l); xhi[i] = h; xlo[i] = l;
    } else if (i < N4X + N4W) {
        int j = i - N4X;
        split_pack(W1[j], h, l); w1hi[j] = h; w1lo[j] = l;
    } else if (i < N4X + 2 * N4W) {
        int j = i - N4X - N4W;
        split_pack(W2[j], h, l); w2hi[j] = h; w2lo[j] = l;
    }
}

// ---------------- gating (+ output zeroing folded in) ----------------
__global__ void k_gate(const float* __restrict__ x, const float* __restrict__ Wg,
                       const float* __restrict__ bg, float* __restrict__ out) {
    {
        float4* o4 = (float4*)out;
        int base = blockIdx.x * 2048;
#pragma unroll
        for (int i = 0; i < 8; i++)
            o4[base + i * 256 + threadIdx.x] = make_float4(0.f, 0.f, 0.f, 0.f);
    }
    float* out_logits = out + (size_t)T_TOK * DM;
    int warp = threadIdx.x >> 5, lane = threadIdx.x & 31;
    int t = blockIdx.x * 8 + warp;
    if (t >= T_TOK) return;
    const float* xr = x + (size_t)t * DM;
    float acc[NE];
#pragma unroll
    for (int e = 0; e < NE; e++) acc[e] = 0.f;
    for (int k = lane; k < DM; k += 32) {
        float xv = xr[k];
        const float* w = Wg + (size_t)k * NE;
#pragma unroll
        for (int e = 0; e < NE; e++) acc[e] += xv * w[e];
    }
#pragma unroll
    for (int e = 0; e < NE; e++)
#pragma unroll
        for (int o = 16; o; o >>= 1) acc[e] += __shfl_xor_sync(0xffffffffu, acc[e], o);
    if (lane == 0) {
#pragma unroll
        for (int e = 0; e < NE; e++) {
            acc[e] += bg[e];
            out_logits[(size_t)t * NE + e] = acc[e];
        }
        int b0 = 0;
#pragma unroll
        for (int e = 1; e < NE; e++) if (acc[e] > acc[b0]) b0 = e;
        int b1 = (b0 == 0) ? 1 : 0;
#pragma unroll
        for (int e = 0; e < NE; e++) if (e != b0 && acc[e] > acc[b1]) b1 = e;
        float ex = expf(acc[b1] - acc[b0]);
        float w0 = 1.f / (1.f + ex);
        float w1 = ex * w0;
        g_eid[2 * t] = b0;     g_ew[2 * t] = w0;
        g_eid[2 * t + 1] = b1; g_ew[2 * t + 1] = w1;
    }
}

// ---------------- routing ----------------
__global__ void k_route() {
    __shared__ int s_cnt[NE], s_cur[NE];
    int tid = threadIdx.x;
    if (tid < NE) s_cnt[tid] = 0;
    __syncthreads();
    for (int a = tid; a < NASSIGN; a += blockDim.x)
        atomicAdd(&s_cnt[g_eid[a]], 1);
    __syncthreads();
    if (tid == 0) {
        int s = 0;
#pragma unroll
        for (int e = 0; e < NE; e++) {
            s_cur[e] = s;
            g_cnt[e] = s_cnt[e]; g_off[e] = s;
            s += s_cnt[e];
        }
    }
    __syncthreads();
    for (int a = tid; a < NASSIGN; a += blockDim.x) {
        int e = g_eid[a];
        int pos = atomicAdd(&s_cur[e], 1);
        g_tok[pos] = a >> 1;
        g_wgt[pos] = g_ew[a];
    }
}

// ---------------- GEMM1: H(bf16 hi/lo) = relu(x @ W1[e] + b1[e]) ----------------
__global__ void __launch_bounds__(512, 1)
k_gemm1_mma(const float* __restrict__ b1) {
    extern __shared__ char dsm[];
    const int e = blockIdx.z;
    const int cnt = g_cnt[e];
    const int m0 = blockIdx.y * 128;
    if (m0 >= cnt) return;
    const int off = g_off[e];
    const int n0 = blockIdx.x * 256;
    const int tid = threadIdx.x;

    uint32_t* rowoff = (uint32_t*)dsm;
    if (tid < 128) {
        int gi = m0 + tid;
        rowoff[tid] = (gi < cnt) ? (uint32_t)(g_tok[off + gi] * DM) : INVALID_ROW;
    }
    __syncthreads();

    float acc[2][8][4];
#pragma unroll
    for (int a = 0; a < 2; a++)
#pragma unroll
        for (int b = 0; b < 8; b++)
#pragma unroll
            for (int c = 0; c < 4; c++) acc[a][b][c] = 0.f;

    mainloop(dsm, g_xhi, g_xlo,
             g_W1hi + (size_t)e * DM * DH, g_W1lo + (size_t)e * DM * DH,
             DH, n0, DM / KC, acc);

    const int lane = tid & 31, w = tid >> 5;
    const int m_warp = (w >> 2) * 32, n_warp = (w & 3) * 64;
    const float* bb = b1 + (size_t)e * DH;
#pragma unroll
    for (int mi = 0; mi < 2; mi++) {
#pragma unroll
        for (int ni = 0; ni < 8; ni++) {
            int col = n0 + n_warp + ni * 8 + (lane & 3) * 2;
            float bc0 = bb[col], bc1 = bb[col + 1];
#pragma unroll
            for (int hr = 0; hr < 2; hr++) {
                int lr = m_warp + mi * 16 + (lane >> 2) + hr * 8;
                int gi = m0 + lr;
                if (gi < cnt) {
                    float h0 = fmaxf(acc[mi][ni][hr * 2 + 0] + bc0, 0.f);
                    float h1 = fmaxf(acc[mi][ni][hr * 2 + 1] + bc1, 0.f);
                    __nv_bfloat16 h0h = __float2bfloat16(h0);
                    __nv_bfloat16 h1h = __float2bfloat16(h1);
                    __nv_bfloat16 h0l = __float2bfloat16(h0 - __bfloat162float(h0h));
                    __nv_bfloat16 h1l = __float2bfloat16(h1 - __bfloat162float(h1h));
                    size_t base = (size_t)(off + gi) * DH + col;
                    *(__nv_bfloat162*)(g_Hhi + base) = __halves2bfloat162(h0h, h1h);
                    *(__nv_bfloat162*)(g_Hlo + base) = __halves2bfloat162(h0l, h1l);
                }
            }
        }
    }
}

// ---------------- GEMM2 (K-split 2): out[tok] += w * (H @ W2[e] + b2[e]) ----------------
__global__ void __launch_bounds__(512, 1)
k_gemm2_mma(const float* __restrict__ b2, float* __restrict__ out) {
    extern __shared__ char dsm[];
    const int e = blockIdx.z >> 1;
    const int half = blockIdx.z & 1;
    const int cnt = g_cnt[e];
    const int m0 = blockIdx.y * 128;
    if (m0 >= cnt) return;
    const int off = g_off[e];
    const int n0 = blockIdx.x * 256;
    const int koff = half * (DH / 2);
    const int tid = threadIdx.x;

    uint32_t* rowoff = (uint32_t*)dsm;
    int* toks = (int*)(dsm + 512);
    float* wgts = (float*)(dsm + 1024);
    if (tid < 128) {
        int gi = m0 + tid;
        bool v = gi < cnt;
        rowoff[tid] = v ? (uint32_t)((off + gi) * DH + koff) : INVALID_ROW;
        toks[tid] = v ? g_tok[off + gi] : 0;
        wgts[tid] = v ? g_wgt[off + gi] : 0.f;
    }
    __syncthreads();

    float acc[2][8][4];
#pragma unroll
    for (int a = 0; a < 2; a++)
#pragma unroll
        for (int b = 0; b < 8; b++)
#pragma unroll
            for (int c = 0; c < 4; c++) acc[a][b][c] = 0.f;

    mainloop(dsm, g_Hhi, g_Hlo,
             g_W2hi + (size_t)e * DH * DM + (size_t)koff * DM,
             g_W2lo + (size_t)e * DH * DM + (size_t)koff * DM,
             DM, n0, (DH / 2) / KC, acc);

    const int lane = tid & 31, w = tid >> 5;
    const int m_warp = (w >> 2) * 32, n_warp = (w & 3) * 64;
    const float* bb = b2 + (size_t)e * DM;
#pragma unroll
    for (int mi = 0; mi < 2; mi++) {
#pragma unroll
        for (int ni = 0; ni < 8; ni++) {
            int col = n0 + n_warp + ni * 8 + (lane & 3) * 2;
            float bc0 = half ? 0.f : bb[col];
            float bc1 = half ? 0.f : bb[col + 1];
#pragma unroll
            for (int hr = 0; hr < 2; hr++) {
                int lr = m_warp + mi * 16 + (lane >> 2) + hr * 8;
                int gi = m0 + lr;
                if (gi < cnt) {
                    int tok  = toks[lr];
                    float wv = wgts[lr];
                    float* orow = out + (size_t)tok * DM + col;
                    atomicAdd(orow,     wv * (acc[mi][ni][hr * 2 + 0] + bc0));
                    atomicAdd(orow + 1, wv * (acc[mi][ni][hr * 2 + 1] + bc1));
                }
            }
        }
    }
}

// ---------------- launch ----------------
extern "C" void kernel_launch(void* const* d_in, const int* in_sizes, int n_in,
                              void* d_out, int out_size) {
    const float* x  = (const float*)d_in[0];
    const float* Wg = (const float*)d_in[1];
    const float* bg = (const float*)d_in[2];
    const float* W1 = (const float*)d_in[3];
    const float* b1 = (const float*)d_in[4];
    const float* W2 = (const float*)d_in[5];
    const float* b2 = (const float*)d_in[6];
    float* out = (float*)d_out;

    cudaFuncSetAttribute(k_gemm1_mma, cudaFuncAttributeMaxDynamicSharedMemorySize, SMEM_TOTAL);
    cudaFuncSetAttribute(k_gemm2_mma, cudaFuncAttributeMaxDynamicSharedMemorySize, SMEM_TOTAL);

    void *p_xhi, *p_xlo, *p_w1hi, *p_w1lo, *p_w2hi, *p_w2lo;
    cudaGetSymbolAddress(&p_xhi,  g_xhi);
    cudaGetSymbolAddress(&p_xlo,  g_xlo);
    cudaGetSymbolAddress(&p_w1hi, g_W1hi);
    cudaGetSymbolAddress(&p_w1lo, g_W1lo);
    cudaGetSymbolAddress(&p_w2hi, g_W2hi);
    cudaGetSymbolAddress(&p_w2lo, g_W2lo);

    {
        int total = N4X + 2 * N4W;
        k_conv_all<<<(total + 255) / 256, 256>>>(
            (const float4*)x, (const float4*)W1, (const float4*)W2,
            (uint2*)p_xhi, (uint2*)p_xlo, (uint2*)p_w1hi, (uint2*)p_w1lo,
            (uint2*)p_w2hi, (uint2*)p_w2lo);
    }
    k_gate<<<T_TOK / 8, 256>>>(x, Wg, bg, out);
    k_route<<<1, 1024>>>();
    k_gemm1_mma<<<dim3(DH / 256, T_TOK / 128, NE), 512, SMEM_TOTAL>>>(b1);
    k_gemm2_mma<<<dim3(DM / 256, T_TOK / 128, NE * 2), 512, SMEM_TOTAL>>>(b2, out);
}

// round 9
// speedup vs baseline: 3.7695x; 1.3135x over previous
#include <cuda_runtime.h>
#include <cuda_fp16.h>
#include <cstdint>
#include <math.h>

#define T_TOK    4096
#define DM       1024
#define DH       4096
#define NE       8
#define NASSIGN  (T_TOK * 2)

#define KC    32
#define PA    40           // A smem pitch (fp16): 32 + 8 pad
#define PB    264          // B smem pitch (fp16): 256 + 8 pad
#define NSTG  4

// stage layout (bytes)
#define ST_AH    0
#define ST_BHI   10240     // 128*PA*2
#define ST_BLO   27136     // +32*PB*2 = 16896
#define ST_BYTES 44032
#define SM_HDR   2048
#define SMEM_TOTAL (SM_HDR + NSTG * ST_BYTES)   // 178176

#define INVALID_ROW 0xFFFFFFFFu
#define N4X (T_TOK * DM / 4)
#define N4W (NE * DM * DH / 4)

// ---------------- static device scratch ----------------
__device__ __half g_xh [(size_t)T_TOK * DM];
__device__ __half g_W1h[(size_t)NE * DM * DH];
__device__ __half g_W1l[(size_t)NE * DM * DH];
__device__ __half g_W2h[(size_t)NE * DH * DM];
__device__ __half g_W2l[(size_t)NE * DH * DM];
__device__ __half g_Hh [(size_t)NASSIGN * DH];
__device__ int   g_tok[NASSIGN];
__device__ float g_wgt[NASSIGN];
__device__ int   g_eid[NASSIGN];
__device__ float g_ew [NASSIGN];
__device__ int   g_cnt[NE];
__device__ int   g_off[NE];

// ---------------- helpers ----------------
__device__ __forceinline__ uint32_t smem_u32(const void* p) {
    uint32_t a;
    asm("{ .reg .u64 t; cvta.to.shared.u64 t, %1; cvt.u32.u64 %0, t; }" : "=r"(a) : "l"(p));
    return a;
}
// fp16 split: hi = fp16(v), lo = fp16(v - hi)
__device__ __forceinline__ void split_pack_h(float4 v, uint2& hi, uint2& lo) {
    __half hx = __float2half(v.x), hy = __float2half(v.y);
    __half hz = __float2half(v.z), hw = __float2half(v.w);
    __half lx = __float2half(v.x - __half2float(hx));
    __half ly = __float2half(v.y - __half2float(hy));
    __half lz = __float2half(v.z - __half2float(hz));
    __half lw = __float2half(v.w - __half2float(hw));
    __half2 h01 = __halves2half2(hx, hy), h23 = __halves2half2(hz, hw);
    __half2 l01 = __halves2half2(lx, ly), l23 = __halves2half2(lz, lw);
    hi.x = *(uint32_t*)&h01; hi.y = *(uint32_t*)&h23;
    lo.x = *(uint32_t*)&l01; lo.y = *(uint32_t*)&l23;
}
__device__ __forceinline__ uint2 pack4_h(float4 v) {
    __half2 h01 = __halves2half2(__float2half(v.x), __float2half(v.y));
    __half2 h23 = __halves2half2(__float2half(v.z), __float2half(v.w));
    uint2 r;
    r.x = *(uint32_t*)&h01; r.y = *(uint32_t*)&h23;
    return r;
}
__device__ __forceinline__ void ldsm_x4(uint32_t (&d)[4], uint32_t addr) {
    asm volatile("ldmatrix.sync.aligned.m8n8.x4.shared.b16 {%0,%1,%2,%3}, [%4];"
        : "=r"(d[0]), "=r"(d[1]), "=r"(d[2]), "=r"(d[3]) : "r"(addr));
}
__device__ __forceinline__ void ldsm_x4t(uint32_t (&d)[4], uint32_t addr) {
    asm volatile("ldmatrix.sync.aligned.m8n8.x4.trans.shared.b16 {%0,%1,%2,%3}, [%4];"
        : "=r"(d[0]), "=r"(d[1]), "=r"(d[2]), "=r"(d[3]) : "r"(addr));
}
__device__ __forceinline__ void mma_f16(float (&d)[4], const uint32_t (&a)[4],
                                         uint32_t b0, uint32_t b1) {
    asm volatile("mma.sync.aligned.m16n8k16.row.col.f32.f16.f16.f32 "
        "{%0,%1,%2,%3},{%4,%5,%6,%7},{%8,%9},{%0,%1,%2,%3};"
        : "+f"(d[0]), "+f"(d[1]), "+f"(d[2]), "+f"(d[3])
        : "r"(a[0]), "r"(a[1]), "r"(a[2]), "r"(a[3]), "r"(b0), "r"(b1));
}
__device__ __forceinline__ void cp16(uint32_t dst, const void* src, uint32_t sz) {
    asm volatile("cp.async.cg.shared.global [%0], [%1], 16, %2;"
                 :: "r"(dst), "l"(src), "r"(sz));
}
#define CP_COMMIT() asm volatile("cp.async.commit_group;" ::: "memory")
#define CP_WAIT2()  asm volatile("cp.async.wait_group 2;" ::: "memory")

// ---------------- issue one KC=32 x (128 A-rows, 256 B-cols) chunk ----------------
__device__ __forceinline__ void issue_chunk(
    uint32_t st, const __half* __restrict__ Ah, const uint32_t* __restrict__ rowoff,
    const __half* __restrict__ Bh, const __half* __restrict__ Bl,
    int ldb, int n0, int k0, int tid)
{
    // A (hi only): 128 rows x 32 k; thread -> (row = tid>>2, 16B-quarter = tid&3)
    const int ar = tid >> 2, aq = tid & 3;
    uint32_t ro = rowoff[ar];
    uint32_t sz = (ro != INVALID_ROW) ? 16u : 0u;
    uint32_t roc = (ro != INVALID_ROW) ? ro : 0u;
    cp16(st + ST_AH + ar * (PA * 2) + aq * 16, Ah + roc + k0 + aq * 8, sz);

    // B: 32 k-rows x 256 n; thread -> (krow = tid>>4, 2 x 16B segs: tid&15, +16)
    const int br = tid >> 4, bs = tid & 15;
    const __half* sbh = Bh + (size_t)(k0 + br) * ldb + n0;
    const __half* sbl = Bl + (size_t)(k0 + br) * ldb + n0;
    uint32_t dbh = st + ST_BHI + br * (PB * 2);
    uint32_t dbl = st + ST_BLO + br * (PB * 2);
    cp16(dbh + bs * 16,        sbh + bs * 8,        16u);
    cp16(dbh + (bs + 16) * 16, sbh + (bs + 16) * 8, 16u);
    cp16(dbl + bs * 16,        sbl + bs * 8,        16u);
    cp16(dbl + (bs + 16) * 16, sbl + (bs + 16) * 8, 16u);
}

// ---------------- compute one chunk (fp16 2-term), warp tile 32x64 ----------------
__device__ __forceinline__ void compute_chunk(
    uint32_t aH, uint32_t bHi, uint32_t bLo, float (&acc)[2][8][4])
{
#pragma unroll
    for (int ks = 0; ks < 2; ks++) {
        uint32_t ah[2][4];
#pragma unroll
        for (int mi = 0; mi < 2; mi++)
            ldsm_x4(ah[mi], aH + ks * 32 + mi * (16 * PA * 2));
#pragma unroll
        for (int njp = 0; njp < 2; njp++) {       // two n32 halves of the n64 tile
            uint32_t bh[2][4], bl[2][4];
#pragma unroll
            for (int j = 0; j < 2; j++) {
                uint32_t boff = ks * (16 * PB * 2) + (njp * 2 + j) * 32;
                ldsm_x4t(bh[j], bHi + boff);
                ldsm_x4t(bl[j], bLo + boff);
            }
#pragma unroll
            for (int mi = 0; mi < 2; mi++)
#pragma unroll
                for (int j = 0; j < 2; j++)
#pragma unroll
                    for (int h = 0; h < 2; h++) {
                        int ni = njp * 4 + j * 2 + h;
                        mma_f16(acc[mi][ni], ah[mi], bh[j][h * 2], bh[j][h * 2 + 1]);
                        mma_f16(acc[mi][ni], ah[mi], bl[j][h * 2], bl[j][h * 2 + 1]);
                    }
        }
    }
}

// ---------------- shared mainloop (512 threads, 16 warps, CTA 128x256) ----------------
__device__ __forceinline__ void mainloop(
    char* dsm, const __half* Ah, const __half* Bh, const __half* Bl,
    int ldb, int n0, int nch, float (&acc)[2][8][4])
{
    const int tid = threadIdx.x;
    const uint32_t sb = smem_u32(dsm);
    const uint32_t* rowoff = (const uint32_t*)dsm;

    const int lane = tid & 31, w = tid >> 5;
    const int m_warp = (w >> 2) * 32, n_warp = (w & 3) * 64;
    const int g = lane >> 3, r = lane & 7;
    const uint32_t a_lane = (uint32_t)(((m_warp + (g & 1) * 8 + r) * PA + (g >> 1) * 8) * 2);
    const uint32_t b_lane = (uint32_t)((((g & 1) * 8 + r) * PB + n_warp + (g >> 1) * 8) * 2);

    uint32_t stg[NSTG];
#pragma unroll
    for (int s = 0; s < NSTG; s++) stg[s] = sb + SM_HDR + s * ST_BYTES;

    issue_chunk(stg[0], Ah, rowoff, Bh, Bl, ldb, n0, 0, tid);
    CP_COMMIT();
    issue_chunk(stg[1], Ah, rowoff, Bh, Bl, ldb, n0, KC, tid);
    CP_COMMIT();

    for (int c = 0; c < nch; c++) {
        if (c + 2 < nch)
            issue_chunk(stg[(c + 2) & 3], Ah, rowoff, Bh, Bl, ldb, n0, (c + 2) * KC, tid);
        CP_COMMIT();
        CP_WAIT2();
        __syncthreads();
        uint32_t st = stg[c & 3];
        compute_chunk(st + ST_AH + a_lane, st + ST_BHI + b_lane, st + ST_BLO + b_lane, acc);
    }
}

// ---------------- fused conversion: x -> fp16; W1, W2 -> fp16 hi/lo ----------------
__global__ void k_conv_all(const float4* __restrict__ x, const float4* __restrict__ W1,
                           const float4* __restrict__ W2,
                           uint2* __restrict__ xh,
                           uint2* __restrict__ w1h, uint2* __restrict__ w1l,
                           uint2* __restrict__ w2h, uint2* __restrict__ w2l) {
    int i = blockIdx.x * blockDim.x + threadIdx.x;
    uint2 h, l;
    if (i < N4X) {
        xh[i] = pack4_h(x[i]);
    } else if (i < N4X + N4W) {
        int j = i - N4X;
        split_pack_h(W1[j], h, l); w1h[j] = h; w1l[j] = l;
    } else if (i < N4X + 2 * N4W) {
        int j = i - N4X - N4W;
        split_pack_h(W2[j], h, l); w2h[j] = h; w2l[j] = l;
    }
}

// ---------------- gating (+ output zeroing folded in) ----------------
__global__ void k_gate(const float* __restrict__ x, const float* __restrict__ Wg,
                       const float* __restrict__ bg, float* __restrict__ out) {
    {
        float4* o4 = (float4*)out;
        int base = blockIdx.x * 2048;
#pragma unroll
        for (int i = 0; i < 8; i++)
            o4[base + i * 256 + threadIdx.x] = make_float4(0.f, 0.f, 0.f, 0.f);
    }
    float* out_logits = out + (size_t)T_TOK * DM;
    int warp = threadIdx.x >> 5, lane = threadIdx.x & 31;
    int t = blockIdx.x * 8 + warp;
    if (t >= T_TOK) return;
    const float* xr = x + (size_t)t * DM;
    float acc[NE];
#pragma unroll
    for (int e = 0; e < NE; e++) acc[e] = 0.f;
    for (int k = lane; k < DM; k += 32) {
        float xv = xr[k];
        const float* w = Wg + (size_t)k * NE;
#pragma unroll
        for (int e = 0; e < NE; e++) acc[e] += xv * w[e];
    }
#pragma unroll
    for (int e = 0; e < NE; e++)
#pragma unroll
        for (int o = 16; o; o >>= 1) acc[e] += __shfl_xor_sync(0xffffffffu, acc[e], o);
    if (lane == 0) {
#pragma unroll
        for (int e = 0; e < NE; e++) {
            acc[e] += bg[e];
            out_logits[(size_t)t * NE + e] = acc[e];
        }
        int b0 = 0;
#pragma unroll
        for (int e = 1; e < NE; e++) if (acc[e] > acc[b0]) b0 = e;
        int b1 = (b0 == 0) ? 1 : 0;
#pragma unroll
        for (int e = 0; e < NE; e++) if (e != b0 && acc[e] > acc[b1]) b1 = e;
        float ex = expf(acc[b1] - acc[b0]);
        float w0 = 1.f / (1.f + ex);
        float w1 = ex * w0;
        g_eid[2 * t] = b0;     g_ew[2 * t] = w0;
        g_eid[2 * t + 1] = b1; g_ew[2 * t + 1] = w1;
    }
}

// ---------------- routing ----------------
__global__ void k_route() {
    __shared__ int s_cnt[NE], s_cur[NE];
    int tid = threadIdx.x;
    if (tid < NE) s_cnt[tid] = 0;
    __syncthreads();
    for (int a = tid; a < NASSIGN; a += blockDim.x)
        atomicAdd(&s_cnt[g_eid[a]], 1);
    __syncthreads();
    if (tid == 0) {
        int s = 0;
#pragma unroll
        for (int e = 0; e < NE; e++) {
            s_cur[e] = s;
            g_cnt[e] = s_cnt[e]; g_off[e] = s;
            s += s_cnt[e];
        }
    }
    __syncthreads();
    for (int a = tid; a < NASSIGN; a += blockDim.x) {
        int e = g_eid[a];
        int pos = atomicAdd(&s_cur[e], 1);
        g_tok[pos] = a >> 1;
        g_wgt[pos] = g_ew[a];
    }
}

// ---------------- GEMM1: H(fp16) = relu(x @ W1[e] + b1[e]) ----------------
__global__ void __launch_bounds__(512, 1)
k_gemm1_mma(const float* __restrict__ b1) {
    extern __shared__ char dsm[];
    const int e = blockIdx.z;
    const int cnt = g_cnt[e];
    const int m0 = blockIdx.y * 128;
    if (m0 >= cnt) return;
    const int off = g_off[e];
    const int n0 = blockIdx.x * 256;
    const int tid = threadIdx.x;

    uint32_t* rowoff = (uint32_t*)dsm;
    if (tid < 128) {
        int gi = m0 + tid;
        rowoff[tid] = (gi < cnt) ? (uint32_t)(g_tok[off + gi] * DM) : INVALID_ROW;
    }
    __syncthreads();

    float acc[2][8][4];
#pragma unroll
    for (int a = 0; a < 2; a++)
#pragma unroll
        for (int b = 0; b < 8; b++)
#pragma unroll
            for (int c = 0; c < 4; c++) acc[a][b][c] = 0.f;

    mainloop(dsm, g_xh,
             g_W1h + (size_t)e * DM * DH, g_W1l + (size_t)e * DM * DH,
             DH, n0, DM / KC, acc);

    const int lane = tid & 31, w = tid >> 5;
    const int m_warp = (w >> 2) * 32, n_warp = (w & 3) * 64;
    const float* bb = b1 + (size_t)e * DH;
#pragma unroll
    for (int mi = 0; mi < 2; mi++) {
#pragma unroll
        for (int ni = 0; ni < 8; ni++) {
            int col = n0 + n_warp + ni * 8 + (lane & 3) * 2;
            float bc0 = bb[col], bc1 = bb[col + 1];
#pragma unroll
            for (int hr = 0; hr < 2; hr++) {
                int lr = m_warp + mi * 16 + (lane >> 2) + hr * 8;
                int gi = m0 + lr;
                if (gi < cnt) {
                    float h0 = fmaxf(acc[mi][ni][hr * 2 + 0] + bc0, 0.f);
                    float h1 = fmaxf(acc[mi][ni][hr * 2 + 1] + bc1, 0.f);
                    __half2 hv = __halves2half2(__float2half(h0), __float2half(h1));
                    *(__half2*)(g_Hh + (size_t)(off + gi) * DH + col) = hv;
                }
            }
        }
    }
}

// ---------------- GEMM2 (K-split 2): out[tok] += w * (H @ W2[e] + b2[e]) ----------------
__global__ void __launch_bounds__(512, 1)
k_gemm2_mma(const float* __restrict__ b2, float* __restrict__ out) {
    extern __shared__ char dsm[];
    const int e = blockIdx.z >> 1;
    const int half = blockIdx.z & 1;
    const int cnt = g_cnt[e];
    const int m0 = blockIdx.y * 128;
    if (m0 >= cnt) return;
    const int off = g_off[e];
    const int n0 = blockIdx.x * 256;
    const int koff = half * (DH / 2);
    const int tid = threadIdx.x;

    uint32_t* rowoff = (uint32_t*)dsm;
    int* toks = (int*)(dsm + 512);
    float* wgts = (float*)(dsm + 1024);
    if (tid < 128) {
        int gi = m0 + tid;
        bool v = gi < cnt;
        rowoff[tid] = v ? (uint32_t)((off + gi) * DH + koff) : INVALID_ROW;
        toks[tid] = v ? g_tok[off + gi] : 0;
        wgts[tid] = v ? g_wgt[off + gi] : 0.f;
    }
    __syncthreads();

    float acc[2][8][4];
#pragma unroll
    for (int a = 0; a < 2; a++)
#pragma unroll
        for (int b = 0; b < 8; b++)
#pragma unroll
            for (int c = 0; c < 4; c++) acc[a][b][c] = 0.f;

    mainloop(dsm, g_Hh,
             g_W2h + (size_t)e * DH * DM + (size_t)koff * DM,
             g_W2l + (size_t)e * DH * DM + (size_t)koff * DM,
             DM, n0, (DH / 2) / KC, acc);

    const int lane = tid & 31, w = tid >> 5;
    const int m_warp = (w >> 2) * 32, n_warp = (w & 3) * 64;
    const float* bb = b2 + (size_t)e * DM;
#pragma unroll
    for (int mi = 0; mi < 2; mi++) {
#pragma unroll
        for (int ni = 0; ni < 8; ni++) {
            int col = n0 + n_warp + ni * 8 + (lane & 3) * 2;
            float bc0 = half ? 0.f : bb[col];
            float bc1 = half ? 0.f : bb[col + 1];
#pragma unroll
            for (int hr = 0; hr < 2; hr++) {
                int lr = m_warp + mi * 16 + (lane >> 2) + hr * 8;
                int gi = m0 + lr;
                if (gi < cnt) {
                    int tok  = toks[lr];
                    float wv = wgts[lr];
                    float* orow = out + (size_t)tok * DM + col;
                    atomicAdd(orow,     wv * (acc[mi][ni][hr * 2 + 0] + bc0));
                    atomicAdd(orow + 1, wv * (acc[mi][ni][hr * 2 + 1] + bc1));
                }
            }
        }
    }
}

// ---------------- launch ----------------
extern "C" void kernel_launch(void* const* d_in, const int* in_sizes, int n_in,
                              void* d_out, int out_size) {
    const float* x  = (const float*)d_in[0];
    const float* Wg = (const float*)d_in[1];
    const float* bg = (const float*)d_in[2];
    const float* W1 = (const float*)d_in[3];
    const float* b1 = (const float*)d_in[4];
    const float* W2 = (const float*)d_in[5];
    const float* b2 = (const float*)d_in[6];
    float* out = (float*)d_out;

    cudaFuncSetAttribute(k_gemm1_mma, cudaFuncAttributeMaxDynamicSharedMemorySize, SMEM_TOTAL);
    cudaFuncSetAttribute(k_gemm2_mma, cudaFuncAttributeMaxDynamicSharedMemorySize, SMEM_TOTAL);

    void *p_xh, *p_w1h, *p_w1l, *p_w2h, *p_w2l;
    cudaGetSymbolAddress(&p_xh,  g_xh);
    cudaGetSymbolAddress(&p_w1h, g_W1h);
    cudaGetSymbolAddress(&p_w1l, g_W1l);
    cudaGetSymbolAddress(&p_w2h, g_W2h);
    cudaGetSymbolAddress(&p_w2l, g_W2l);

    {
        int total = N4X + 2 * N4W;
        k_conv_all<<<(total + 255) / 256, 256>>>(
            (const float4*)x, (const float4*)W1, (const float4*)W2,
            (uint2*)p_xh, (uint2*)p_w1h, (uint2*)p_w1l, (uint2*)p_w2h, (uint2*)p_w2l);
    }
    k_gate<<<T_TOK / 8, 256>>>(x, Wg, bg, out);
    k_route<<<1, 1024>>>();
    k_gemm1_mma<<<dim3(DH / 256, T_TOK / 128, NE), 512, SMEM_TOTAL>>>(b1);
    k_gemm2_mma<<<dim3(DM / 256, T_TOK / 128, NE * 2), 512, SMEM_TOTAL>>>(b2, out);
}

// round 10
// speedup vs baseline: 5.8108x; 1.5415x over previous
#include <cuda_runtime.h>
#include <cuda_fp16.h>
#include <cstdint>
#include <math.h>

#define T_TOK    4096
#define DM       1024
#define DH       4096
#define NE       8
#define NASSIGN  (T_TOK * 2)

#define KC    32
#define PA    40           // A smem pitch (fp16): 32 + 8 pad
#define PB    264          // B smem pitch (fp16): 256 + 8 pad
#define NSTG  4

// stage layout (bytes)
#define ST_AH    0
#define ST_BH    10240     // 128*PA*2
#define ST_BYTES 27136     // + 32*PB*2 = 16896
#define SM_HDR   2048
#define SMEM_TOTAL (SM_HDR + NSTG * ST_BYTES)   // 110592

#define INVALID_ROW 0xFFFFFFFFu
#define N4X (T_TOK * DM / 4)
#define N4W (NE * DM * DH / 4)

// ---------------- static device scratch ----------------
__device__ __half g_xh [(size_t)T_TOK * DM];
__device__ __half g_W1h[(size_t)NE * DM * DH];
__device__ __half g_W2h[(size_t)NE * DH * DM];
__device__ __half g_Hh [(size_t)NASSIGN * DH];
__device__ int   g_tok[NASSIGN];
__device__ float g_wgt[NASSIGN];
__device__ int   g_eid[NASSIGN];
__device__ float g_ew [NASSIGN];
__device__ int   g_cnt[NE];
__device__ int   g_off[NE];

// ---------------- helpers ----------------
__device__ __forceinline__ uint32_t smem_u32(const void* p) {
    uint32_t a;
    asm("{ .reg .u64 t; cvta.to.shared.u64 t, %1; cvt.u32.u64 %0, t; }" : "=r"(a) : "l"(p));
    return a;
}
__device__ __forceinline__ uint2 pack4_h(float4 v) {
    __half2 h01 = __halves2half2(__float2half(v.x), __float2half(v.y));
    __half2 h23 = __halves2half2(__float2half(v.z), __float2half(v.w));
    uint2 r;
    r.x = *(uint32_t*)&h01; r.y = *(uint32_t*)&h23;
    return r;
}
__device__ __forceinline__ void ldsm_x4(uint32_t (&d)[4], uint32_t addr) {
    asm volatile("ldmatrix.sync.aligned.m8n8.x4.shared.b16 {%0,%1,%2,%3}, [%4];"
        : "=r"(d[0]), "=r"(d[1]), "=r"(d[2]), "=r"(d[3]) : "r"(addr));
}
__device__ __forceinline__ void ldsm_x4t(uint32_t (&d)[4], uint32_t addr) {
    asm volatile("ldmatrix.sync.aligned.m8n8.x4.trans.shared.b16 {%0,%1,%2,%3}, [%4];"
        : "=r"(d[0]), "=r"(d[1]), "=r"(d[2]), "=r"(d[3]) : "r"(addr));
}
__device__ __forceinline__ void mma_f16(float (&d)[4], const uint32_t (&a)[4],
                                         uint32_t b0, uint32_t b1) {
    asm volatile("mma.sync.aligned.m16n8k16.row.col.f32.f16.f16.f32 "
        "{%0,%1,%2,%3},{%4,%5,%6,%7},{%8,%9},{%0,%1,%2,%3};"
        : "+f"(d[0]), "+f"(d[1]), "+f"(d[2]), "+f"(d[3])
        : "r"(a[0]), "r"(a[1]), "r"(a[2]), "r"(a[3]), "r"(b0), "r"(b1));
}
__device__ __forceinline__ void cp16(uint32_t dst, const void* src, uint32_t sz) {
    asm volatile("cp.async.cg.shared.global [%0], [%1], 16, %2;"
                 :: "r"(dst), "l"(src), "r"(sz));
}
#define CP_COMMIT() asm volatile("cp.async.commit_group;" ::: "memory")
#define CP_WAIT2()  asm volatile("cp.async.wait_group 2;" ::: "memory")

// ---------------- issue one KC=32 x (128 A-rows, 256 B-cols) chunk ----------------
__device__ __forceinline__ void issue_chunk(
    uint32_t st, const __half* __restrict__ Ah, const uint32_t* __restrict__ rowoff,
    const __half* __restrict__ Bh, int ldb, int n0, int k0, int tid)
{
    // A: 128 rows x 32 k; thread -> (row = tid>>2, 16B-quarter = tid&3)
    const int ar = tid >> 2, aq = tid & 3;
    uint32_t ro = rowoff[ar];
    uint32_t sz = (ro != INVALID_ROW) ? 16u : 0u;
    uint32_t roc = (ro != INVALID_ROW) ? ro : 0u;
    cp16(st + ST_AH + ar * (PA * 2) + aq * 16, Ah + roc + k0 + aq * 8, sz);

    // B: 32 k-rows x 256 n; thread -> (krow = tid>>4, 2 x 16B segs: tid&15, +16)
    const int br = tid >> 4, bs = tid & 15;
    const __half* sbh = Bh + (size_t)(k0 + br) * ldb + n0;
    uint32_t dbh = st + ST_BH + br * (PB * 2);
    cp16(dbh + bs * 16,        sbh + bs * 8,        16u);
    cp16(dbh + (bs + 16) * 16, sbh + (bs + 16) * 8, 16u);
}

// ---------------- compute one chunk (pure fp16), warp tile 32x64 ----------------
__device__ __forceinline__ void compute_chunk(
    uint32_t aH, uint32_t bH, float (&acc)[2][8][4])
{
#pragma unroll
    for (int ks = 0; ks < 2; ks++) {
        uint32_t ah[2][4];
#pragma unroll
        for (int mi = 0; mi < 2; mi++)
            ldsm_x4(ah[mi], aH + ks * 32 + mi * (16 * PA * 2));
#pragma unroll
        for (int njp = 0; njp < 2; njp++) {       // two n32 halves of the n64 tile
            uint32_t bh[2][4];
#pragma unroll
            for (int j = 0; j < 2; j++)
                ldsm_x4t(bh[j], bH + ks * (16 * PB * 2) + (njp * 2 + j) * 32);
#pragma unroll
            for (int mi = 0; mi < 2; mi++)
#pragma unroll
                for (int j = 0; j < 2; j++)
#pragma unroll
                    for (int h = 0; h < 2; h++)
                        mma_f16(acc[mi][njp * 4 + j * 2 + h], ah[mi],
                                bh[j][h * 2], bh[j][h * 2 + 1]);
        }
    }
}

// ---------------- shared mainloop (512 threads, 16 warps, CTA 128x256) ----------------
__device__ __forceinline__ void mainloop(
    char* dsm, const __half* Ah, const __half* Bh,
    int ldb, int n0, int nch, float (&acc)[2][8][4])
{
    const int tid = threadIdx.x;
    const uint32_t sb = smem_u32(dsm);
    const uint32_t* rowoff = (const uint32_t*)dsm;

    const int lane = tid & 31, w = tid >> 5;
    const int m_warp = (w >> 2) * 32, n_warp = (w & 3) * 64;
    const int g = lane >> 3, r = lane & 7;
    const uint32_t a_lane = (uint32_t)(((m_warp + (g & 1) * 8 + r) * PA + (g >> 1) * 8) * 2);
    const uint32_t b_lane = (uint32_t)((((g & 1) * 8 + r) * PB + n_warp + (g >> 1) * 8) * 2);

    uint32_t stg[NSTG];
#pragma unroll
    for (int s = 0; s < NSTG; s++) stg[s] = sb + SM_HDR + s * ST_BYTES;

    issue_chunk(stg[0], Ah, rowoff, Bh, ldb, n0, 0, tid);
    CP_COMMIT();
    issue_chunk(stg[1], Ah, rowoff, Bh, ldb, n0, KC, tid);
    CP_COMMIT();

    for (int c = 0; c < nch; c++) {
        if (c + 2 < nch)
            issue_chunk(stg[(c + 2) & 3], Ah, rowoff, Bh, ldb, n0, (c + 2) * KC, tid);
        CP_COMMIT();
        CP_WAIT2();
        __syncthreads();
        uint32_t st = stg[c & 3];
        compute_chunk(st + ST_AH + a_lane, st + ST_BH + b_lane, acc);
    }
}

// ---------------- fused conversion: x, W1, W2 -> fp16 ----------------
__global__ void k_conv_all(const float4* __restrict__ x, const float4* __restrict__ W1,
                           const float4* __restrict__ W2,
                           uint2* __restrict__ xh,
                           uint2* __restrict__ w1h, uint2* __restrict__ w2h) {
    int i = blockIdx.x * blockDim.x + threadIdx.x;
    if (i < N4X) {
        xh[i] = pack4_h(x[i]);
    } else if (i < N4X + N4W) {
        int j = i - N4X;
        w1h[j] = pack4_h(W1[j]);
    } else if (i < N4X + 2 * N4W) {
        int j = i - N4X - N4W;
        w2h[j] = pack4_h(W2[j]);
    }
}

// ---------------- gating (+ output zeroing folded in) ----------------
__global__ void k_gate(const float* __restrict__ x, const float* __restrict__ Wg,
                       const float* __restrict__ bg, float* __restrict__ out) {
    {
        float4* o4 = (float4*)out;
        int base = blockIdx.x * 2048;
#pragma unroll
        for (int i = 0; i < 8; i++)
            o4[base + i * 256 + threadIdx.x] = make_float4(0.f, 0.f, 0.f, 0.f);
    }
    float* out_logits = out + (size_t)T_TOK * DM;
    int warp = threadIdx.x >> 5, lane = threadIdx.x & 31;
    int t = blockIdx.x * 8 + warp;
    if (t >= T_TOK) return;
    const float* xr = x + (size_t)t * DM;
    float acc[NE];
#pragma unroll
    for (int e = 0; e < NE; e++) acc[e] = 0.f;
    for (int k = lane; k < DM; k += 32) {
        float xv = xr[k];
        const float* w = Wg + (size_t)k * NE;
#pragma unroll
        for (int e = 0; e < NE; e++) acc[e] += xv * w[e];
    }
#pragma unroll
    for (int e = 0; e < NE; e++)
#pragma unroll
        for (int o = 16; o; o >>= 1) acc[e] += __shfl_xor_sync(0xffffffffu, acc[e], o);
    if (lane == 0) {
#pragma unroll
        for (int e = 0; e < NE; e++) {
            acc[e] += bg[e];
            out_logits[(size_t)t * NE + e] = acc[e];
        }
        int b0 = 0;
#pragma unroll
        for (int e = 1; e < NE; e++) if (acc[e] > acc[b0]) b0 = e;
        int b1 = (b0 == 0) ? 1 : 0;
#pragma unroll
        for (int e = 0; e < NE; e++) if (e != b0 && acc[e] > acc[b1]) b1 = e;
        float ex = expf(acc[b1] - acc[b0]);
        float w0 = 1.f / (1.f + ex);
        float w1 = ex * w0;
        g_eid[2 * t] = b0;     g_ew[2 * t] = w0;
        g_eid[2 * t + 1] = b1; g_ew[2 * t + 1] = w1;
    }
}

// ---------------- routing ----------------
__global__ void k_route() {
    __shared__ int s_cnt[NE], s_cur[NE];
    int tid = threadIdx.x;
    if (tid < NE) s_cnt[tid] = 0;
    __syncthreads();
    for (int a = tid; a < NASSIGN; a += blockDim.x)
        atomicAdd(&s_cnt[g_eid[a]], 1);
    __syncthreads();
    if (tid == 0) {
        int s = 0;
#pragma unroll
        for (int e = 0; e < NE; e++) {
            s_cur[e] = s;
            g_cnt[e] = s_cnt[e]; g_off[e] = s;
            s += s_cnt[e];
        }
    }
    __syncthreads();
    for (int a = tid; a < NASSIGN; a += blockDim.x) {
        int e = g_eid[a];
        int pos = atomicAdd(&s_cur[e], 1);
        g_tok[pos] = a >> 1;
        g_wgt[pos] = g_ew[a];
    }
}

// ---------------- GEMM1: H(fp16) = relu(x @ W1[e] + b1[e]) ----------------
__global__ void __launch_bounds__(512, 1)
k_gemm1_mma(const float* __restrict__ b1) {
    extern __shared__ char dsm[];
    const int e = blockIdx.z;
    const int cnt = g_cnt[e];
    const int m0 = blockIdx.y * 128;
    if (m0 >= cnt) return;
    const int off = g_off[e];
    const int n0 = blockIdx.x * 256;
    const int tid = threadIdx.x;

    uint32_t* rowoff = (uint32_t*)dsm;
    if (tid < 128) {
        int gi = m0 + tid;
        rowoff[tid] = (gi < cnt) ? (uint32_t)(g_tok[off + gi] * DM) : INVALID_ROW;
    }
    __syncthreads();

    float acc[2][8][4];
#pragma unroll
    for (int a = 0; a < 2; a++)
#pragma unroll
        for (int b = 0; b < 8; b++)
#pragma unroll
            for (int c = 0; c < 4; c++) acc[a][b][c] = 0.f;

    mainloop(dsm, g_xh, g_W1h + (size_t)e * DM * DH, DH, n0, DM / KC, acc);

    const int lane = tid & 31, w = tid >> 5;
    const int m_warp = (w >> 2) * 32, n_warp = (w & 3) * 64;
    const float* bb = b1 + (size_t)e * DH;
#pragma unroll
    for (int mi = 0; mi < 2; mi++) {
#pragma unroll
        for (int ni = 0; ni < 8; ni++) {
            int col = n0 + n_warp + ni * 8 + (lane & 3) * 2;
            float bc0 = bb[col], bc1 = bb[col + 1];
#pragma unroll
            for (int hr = 0; hr < 2; hr++) {
                int lr = m_warp + mi * 16 + (lane >> 2) + hr * 8;
                int gi = m0 + lr;
                if (gi < cnt) {
                    float h0 = fmaxf(acc[mi][ni][hr * 2 + 0] + bc0, 0.f);
                    float h1 = fmaxf(acc[mi][ni][hr * 2 + 1] + bc1, 0.f);
                    __half2 hv = __halves2half2(__float2half(h0), __float2half(h1));
                    *(__half2*)(g_Hh + (size_t)(off + gi) * DH + col) = hv;
                }
            }
        }
    }
}

// ---------------- GEMM2 (K-split 2): out[tok] += w * (H @ W2[e] + b2[e]) ----------------
__global__ void __launch_bounds__(512, 1)
k_gemm2_mma(const float* __restrict__ b2, float* __restrict__ out) {
    extern __shared__ char dsm[];
    const int e = blockIdx.z >> 1;
    const int half = blockIdx.z & 1;
    const int cnt = g_cnt[e];
    const int m0 = blockIdx.y * 128;
    if (m0 >= cnt) return;
    const int off = g_off[e];
    const int n0 = blockIdx.x * 256;
    const int koff = half * (DH / 2);
    const int tid = threadIdx.x;

    uint32_t* rowoff = (uint32_t*)dsm;
    int* toks = (int*)(dsm + 512);
    float* wgts = (float*)(dsm + 1024);
    if (tid < 128) {
        int gi = m0 + tid;
        bool v = gi < cnt;
        rowoff[tid] = v ? (uint32_t)((off + gi) * DH + koff) : INVALID_ROW;
        toks[tid] = v ? g_tok[off + gi] : 0;
        wgts[tid] = v ? g_wgt[off + gi] : 0.f;
    }
    __syncthreads();

    float acc[2][8][4];
#pragma unroll
    for (int a = 0; a < 2; a++)
#pragma unroll
        for (int b = 0; b < 8; b++)
#pragma unroll
            for (int c = 0; c < 4; c++) acc[a][b][c] = 0.f;

    mainloop(dsm, g_Hh, g_W2h + (size_t)e * DH * DM + (size_t)koff * DM,
             DM, n0, (DH / 2) / KC, acc);

    const int lane = tid & 31, w = tid >> 5;
    const int m_warp = (w >> 2) * 32, n_warp = (w & 3) * 64;
    const float* bb = b2 + (size_t)e * DM;
#pragma unroll
    for (int mi = 0; mi < 2; mi++) {
#pragma unroll
        for (int ni = 0; ni < 8; ni++) {
            int col = n0 + n_warp + ni * 8 + (lane & 3) * 2;
            float bc0 = half ? 0.f : bb[col];
            float bc1 = half ? 0.f : bb[col + 1];
#pragma unroll
            for (int hr = 0; hr < 2; hr++) {
                int lr = m_warp + mi * 16 + (lane >> 2) + hr * 8;
                int gi = m0 + lr;
                if (gi < cnt) {
                    int tok  = toks[lr];
                    float wv = wgts[lr];
                    float* orow = out + (size_t)tok * DM + col;
                    atomicAdd(orow,     wv * (acc[mi][ni][hr * 2 + 0] + bc0));
                    atomicAdd(orow + 1, wv * (acc[mi][ni][hr * 2 + 1] + bc1));
                }
            }
        }
    }
}

// ---------------- launch ----------------
extern "C" void kernel_launch(void* const* d_in, const int* in_sizes, int n_in,
                              void* d_out, int out_size) {
    const float* x  = (const float*)d_in[0];
    const float* Wg = (const float*)d_in[1];
    const float* bg = (const float*)d_in[2];
    const float* W1 = (const float*)d_in[3];
    const float* b1 = (const float*)d_in[4];
    const float* W2 = (const float*)d_in[5];
    const float* b2 = (const float*)d_in[6];
    float* out = (float*)d_out;

    cudaFuncSetAttribute(k_gemm1_mma, cudaFuncAttributeMaxDynamicSharedMemorySize, SMEM_TOTAL);
    cudaFuncSetAttribute(k_gemm2_mma, cudaFuncAttributeMaxDynamicSharedMemorySize, SMEM_TOTAL);

    void *p_xh, *p_w1h, *p_w2h;
    cudaGetSymbolAddress(&p_xh,  g_xh);
    cudaGetSymbolAddress(&p_w1h, g_W1h);
    cudaGetSymbolAddress(&p_w2h, g_W2h);

    {
        int total = N4X + 2 * N4W;
        k_conv_all<<<(total + 255) / 256, 256>>>(
            (const float4*)x, (const float4*)W1, (const float4*)W2,
            (uint2*)p_xh, (uint2*)p_w1h, (uint2*)p_w2h);
    }
    k_gate<<<T_TOK / 8, 256>>>(x, Wg, bg, out);
    k_route<<<1, 1024>>>();
    k_gemm1_mma<<<dim3(DH / 256, T_TOK / 128, NE), 512, SMEM_TOTAL>>>(b1);
    k_gemm2_mma<<<dim3(DM / 256, T_TOK / 128, NE * 2), 512, SMEM_TOTAL>>>(b2, out);
}